// round 2
// baseline (speedup 1.0000x reference)
#include <cuda_runtime.h>
#include <math.h>
#include <stdint.h>

#define BB 16
#define NN 4096
#define NP 1024
#define NS 32
#define DIN 64
#define M_TOTAL (BB*NP*NS)   /* 524288 rows of the flattened (b,s,k) axis */

// ---------------------------------------------------------------------------
// Scratch (device globals; no allocation allowed)
// ---------------------------------------------------------------------------
__device__ float  g_pts_t[BB*NN*DIN];        // points transposed [B,N,64]   16 MB
__device__ float  g_new_xyz[BB*NP*3];        // sampled centroids [B,NP,3]
__device__ int    g_idx[M_TOTAL];            // ball-query indices [B,NP,NS]
__device__ float  g_y0[M_TOTAL*64];          // layer0 pre-BN output  134 MB
__device__ float  g_y1[M_TOTAL*64];          // layer1 pre-BN output  134 MB
__device__ float  g_y2[(size_t)M_TOTAL*128]; // layer2 pre-BN output  268 MB
__device__ double g_part[2*256*128];         // partial sums / sumsq
__device__ float  g_mu[128];
__device__ float  g_rs[128];

// ---------------------------------------------------------------------------
// 0) transpose points [B,64,N] -> [B,N,64]
// ---------------------------------------------------------------------------
__global__ void transpose_pts_kernel(const float* __restrict__ pts) {
    __shared__ float tile[32][33];
    int b  = blockIdx.z;
    int n0 = blockIdx.x * 32;
    int c0 = blockIdx.y * 32;
    int tx = threadIdx.x, ty = threadIdx.y;   // 32 x 8
    const float* pb = pts + (size_t)b*DIN*NN;
    #pragma unroll
    for (int i = ty; i < 32; i += 8)
        tile[i][tx] = pb[(size_t)(c0+i)*NN + n0 + tx];
    __syncthreads();
    float* ob = g_pts_t + (size_t)b*NN*DIN;
    #pragma unroll
    for (int i = ty; i < 32; i += 8)
        ob[(size_t)(n0+i)*DIN + c0 + tx] = tile[tx][i];
}

// ---------------------------------------------------------------------------
// 1) Farthest point sampling. One block per batch, 512 threads, 8 pts/thread.
//    Matches jnp.argmax first-max-index tie-break via int-bit max + min-index.
// ---------------------------------------------------------------------------
__global__ void fps_kernel(const float* __restrict__ xyz, float* __restrict__ out) {
    int b = blockIdx.x, tid = threadIdx.x;     // 512 threads
    const float* xb = xyz + (size_t)b*3*NN;
    float px[8], py[8], pz[8], dd[8];
    #pragma unroll
    for (int i = 0; i < 8; i++) {
        int n = tid + i*512;
        px[i] = xb[n]; py[i] = xb[NN+n]; pz[i] = xb[2*NN+n];
        dd[i] = 1e10f;
    }
    __shared__ int      s_fps[NP];
    __shared__ unsigned s_wv[16];
    __shared__ int      s_wi[16];
    __shared__ int      s_far;
    if (tid == 0) s_fps[0] = 0;
    int far = 0;
    for (int it = 1; it < NP; ++it) {
        float cx = __ldg(xb + far);
        float cy = __ldg(xb + NN + far);
        float cz = __ldg(xb + 2*NN + far);
        unsigned bv = 0u, bi = 0x7fffffffu;
        #pragma unroll
        for (int i = 0; i < 8; i++) {
            // reference order: ((dx*dx + dy*dy) + dz*dz), no FMA contraction
            float dx = __fsub_rn(px[i], cx);
            float dy = __fsub_rn(py[i], cy);
            float dz = __fsub_rn(pz[i], cz);
            float d  = __fadd_rn(__fadd_rn(__fmul_rn(dx,dx), __fmul_rn(dy,dy)),
                                 __fmul_rn(dz,dz));
            dd[i] = fminf(dd[i], d);
            unsigned vb = __float_as_uint(dd[i]);   // nonneg fp32: bit order == fp order
            if (vb > bv) { bv = vb; bi = (unsigned)(tid + i*512); } // strict > keeps min idx
        }
        unsigned wmax = __reduce_max_sync(0xffffffffu, bv);
        unsigned cand = (bv == wmax) ? bi : 0x7fffffffu;
        unsigned wi   = __reduce_min_sync(0xffffffffu, cand);
        if ((tid & 31) == 0) { s_wv[tid >> 5] = wmax; s_wi[tid >> 5] = (int)wi; }
        __syncthreads();
        if (tid < 32) {
            unsigned v  = (tid < 16) ? s_wv[tid] : 0u;
            unsigned ix = (tid < 16) ? (unsigned)s_wi[tid] : 0x7fffffffu;
            unsigned m2 = __reduce_max_sync(0xffffffffu, v);
            unsigned c2 = (v == m2) ? ix : 0x7fffffffu;
            unsigned gi = __reduce_min_sync(0xffffffffu, c2);
            if (tid == 0) { s_far = (int)gi; s_fps[it] = (int)gi; }
        }
        __syncthreads();
        far = s_far;
    }
    // write new_xyz: out [B,3,NP] and scratch [B,NP,3]
    for (int s = tid; s < NP; s += 512) {
        int j = s_fps[s];
        float x = xb[j], y = xb[NN+j], z = xb[2*NN+j];
        out[(size_t)b*3*NP + s]        = x;
        out[(size_t)b*3*NP + NP + s]   = y;
        out[(size_t)b*3*NP + 2*NP + s] = z;
        float* nx = g_new_xyz + ((size_t)b*NP + s)*3;
        nx[0] = x; nx[1] = y; nx[2] = z;
    }
}

// ---------------------------------------------------------------------------
// 2) Ball query: one warp per centroid. First 32 in-radius indices (ascending),
//    padded with the first. Distance formula replicates -2*dot + |s|^2 + |d|^2.
// ---------------------------------------------------------------------------
__global__ void ball_query_kernel(const float* __restrict__ xyz) {
    int gt   = blockIdx.x * blockDim.x + threadIdx.x;
    int warp = gt >> 5;
    int lane = gt & 31;
    if (warp >= BB*NP) return;
    int b = warp >> 10;
    const float* xb = xyz + (size_t)b*3*NN;
    const float* nx = g_new_xyz + (size_t)warp*3;
    float cx = nx[0], cy = nx[1], cz = nx[2];
    float ssrc = __fadd_rn(__fadd_rn(__fmul_rn(cx,cx), __fmul_rn(cy,cy)), __fmul_rn(cz,cz));
    const float R2 = 0.04f;
    int cnt = 0, first = -1;
    int* op = g_idx + (size_t)warp*NS;
    for (int j0 = 0; j0 < NN && cnt < NS; j0 += 32) {
        int j = j0 + lane;
        float x = xb[j], y = xb[NN+j], z = xb[2*NN+j];
        float sdst = __fadd_rn(__fadd_rn(__fmul_rn(x,x), __fmul_rn(y,y)), __fmul_rn(z,z));
        float dot  = __fadd_rn(__fadd_rn(__fmul_rn(cx,x), __fmul_rn(cy,y)), __fmul_rn(cz,z));
        float d = __fadd_rn(__fadd_rn(__fmul_rn(-2.0f, dot), ssrc), sdst);
        bool in = !(d > R2);
        unsigned m = __ballot_sync(0xffffffffu, in);
        if (first < 0 && m) first = j0 + __ffs(m) - 1;
        if (in) {
            int slot = cnt + __popc(m & ((1u << lane) - 1u));
            if (slot < NS) op[slot] = j;
        }
        cnt += __popc(m);
    }
    if (cnt < NS) {
        if (first < 0) first = NN - 1;   // matches clip(N, 0, N-1)
        for (int slot = cnt + lane; slot < NS; slot += 32) op[slot] = first;
    }
}

// ---------------------------------------------------------------------------
// GEMM core: 256 rows x 64 cols per block, 256 threads, 8x8 register tile.
// As is row-major with odd pitch so 8-apart row reads hit distinct banks.
// ---------------------------------------------------------------------------
template<int K, int P>
__device__ __forceinline__ void gemm_core(const float* __restrict__ As,
                                          const float* __restrict__ Ws,
                                          int rg, int cg, float acc[8][8]) {
    const float* ap = As + rg*8*P;
    const float* wp = Ws + cg*8;
    for (int k = 0; k < K; ++k) {
        float a[8];
        #pragma unroll
        for (int i = 0; i < 8; i++) a[i] = ap[i*P + k];
        float4 w0 = *(const float4*)(wp + k*64);
        float4 w1 = *(const float4*)(wp + k*64 + 4);
        #pragma unroll
        for (int i = 0; i < 8; i++) {
            acc[i][0] += a[i]*w0.x; acc[i][1] += a[i]*w0.y;
            acc[i][2] += a[i]*w0.z; acc[i][3] += a[i]*w0.w;
            acc[i][4] += a[i]*w1.x; acc[i][5] += a[i]*w1.y;
            acc[i][6] += a[i]*w1.z; acc[i][7] += a[i]*w1.w;
        }
    }
}

// 3) Layer 0: gather (grouped_xyz | grouped_pts) on the fly, K=67 -> 64
__global__ void __launch_bounds__(256, 2)
gemm0_kernel(const float* __restrict__ xyz, const float* __restrict__ w,
             const float* __restrict__ bias) {
    extern __shared__ float sm[];
    float* Ws = sm;            // 67*64
    float* As = sm + 67*64;    // 256*69
    __shared__ int sj[256];
    int tid = threadIdx.x;
    int m0  = blockIdx.x * 256;
    for (int i = tid; i < 67*64; i += 256) Ws[i] = w[i];
    sj[tid] = g_idx[m0 + tid];
    __syncthreads();
    int b = m0 >> 15;                       // 32768 rows per batch, 256 | 32768
    const float* ptb = g_pts_t + (size_t)b*NN*DIN;
    for (int i = tid; i < 256*64; i += 256) {
        int r = i >> 6, c = i & 63;
        As[r*69 + 3 + c] = ptb[(size_t)sj[r]*64 + c];
    }
    const float* xb = xyz + (size_t)b*3*NN;
    for (int i = tid; i < 256*3; i += 256) {
        int r = i / 3, d = i - r*3;
        As[r*69 + d] = __fsub_rn(xb[d*NN + sj[r]], g_new_xyz[((m0+r) >> 5)*3 + d]);
    }
    __syncthreads();
    int rg = tid >> 3, cg = tid & 7;
    float acc[8][8];
    #pragma unroll
    for (int i = 0; i < 8; i++)
        #pragma unroll
        for (int j = 0; j < 8; j++) acc[i][j] = 0.0f;
    gemm_core<67, 69>(As, Ws, rg, cg, acc);
    float bb[8];
    #pragma unroll
    for (int j = 0; j < 8; j++) bb[j] = bias[cg*8 + j];
    #pragma unroll
    for (int i = 0; i < 8; i++) {
        size_t row = (size_t)(m0 + rg*8 + i);
        float4 v0 = make_float4(acc[i][0]+bb[0], acc[i][1]+bb[1], acc[i][2]+bb[2], acc[i][3]+bb[3]);
        float4 v1 = make_float4(acc[i][4]+bb[4], acc[i][5]+bb[5], acc[i][6]+bb[6], acc[i][7]+bb[7]);
        *(float4*)&g_y0[row*64 + cg*8]     = v0;
        *(float4*)&g_y0[row*64 + cg*8 + 4] = v1;
    }
}

// 4) Layers 1/2: BN(prev stats)+ReLU fused into A-load, K=64 -> 64-col slice.
//    gam/bet here are the PREVIOUS layer's BN affine params (applied to yin).
__global__ void __launch_bounds__(256, 2)
gemm_mid_kernel(const float* __restrict__ w, int ldw,
                const float* __restrict__ bias,
                const float* __restrict__ gam, const float* __restrict__ bet,
                int layer) {
    extern __shared__ float sm[];
    float* Ws = sm;            // 64*64
    float* As = sm + 64*64;    // 256*65
    __shared__ float s_mu[64], s_rs[64], s_g[64], s_b[64];
    const float* yin  = (layer == 1) ? g_y0 : g_y1;
    float*       yout = (layer == 1) ? g_y1 : g_y2;
    int ldo = (layer == 1) ? 64 : 128;
    int tid = threadIdx.x;
    int m0  = blockIdx.x * 256;
    int c0  = blockIdx.y * 64;
    if (tid < 64) { s_mu[tid] = g_mu[tid]; s_rs[tid] = g_rs[tid];
                    s_g[tid]  = gam[tid];  s_b[tid]  = bet[tid]; }
    for (int i = tid; i < 64*64; i += 256) {
        int k = i >> 6, c = i & 63;
        Ws[i] = w[k*ldw + c0 + c];
    }
    __syncthreads();
    for (int i = tid; i < 256*64; i += 256) {
        int r = i >> 6, k = i & 63;
        float v = yin[(size_t)(m0 + r)*64 + k];
        v = ((v - s_mu[k]) * s_rs[k]) * s_g[k] + s_b[k];
        As[r*65 + k] = fmaxf(v, 0.0f);
    }
    __syncthreads();
    int rg = tid >> 3, cg = tid & 7;
    float acc[8][8];
    #pragma unroll
    for (int i = 0; i < 8; i++)
        #pragma unroll
        for (int j = 0; j < 8; j++) acc[i][j] = 0.0f;
    gemm_core<64, 65>(As, Ws, rg, cg, acc);
    float bb[8];
    #pragma unroll
    for (int j = 0; j < 8; j++) bb[j] = bias[c0 + cg*8 + j];
    #pragma unroll
    for (int i = 0; i < 8; i++) {
        size_t row = (size_t)(m0 + rg*8 + i);
        float4 v0 = make_float4(acc[i][0]+bb[0], acc[i][1]+bb[1], acc[i][2]+bb[2], acc[i][3]+bb[3]);
        float4 v1 = make_float4(acc[i][4]+bb[4], acc[i][5]+bb[5], acc[i][6]+bb[6], acc[i][7]+bb[7]);
        *(float4*)&yout[row*ldo + c0 + cg*8]     = v0;
        *(float4*)&yout[row*ldo + c0 + cg*8 + 4] = v1;
    }
}

// 5) BN statistics: per-channel sum / sumsq (double), 256 partial blocks
__global__ void reduce_stats_kernel(int which, int C) {
    const float* y = (which == 0) ? g_y0 : (which == 1) ? g_y1 : g_y2;
    int tid = threadIdx.x, blk = blockIdx.x;
    int ch  = tid & (C - 1);
    int rep = tid / C;
    int nrep = 256 / C;
    size_t base = (size_t)blk * 2048;          // M_TOTAL/256 rows per block
    double s = 0.0, q = 0.0;
    for (int r = rep; r < 2048; r += nrep) {
        float v = y[(base + r)*(size_t)C + ch];
        s += (double)v;
        q += (double)v * (double)v;
    }
    __shared__ double shs[256], shq[256];
    shs[tid] = s; shq[tid] = q;
    __syncthreads();
    if (rep == 0) {
        for (int r2 = 1; r2 < nrep; ++r2) { s += shs[r2*C + ch]; q += shq[r2*C + ch]; }
        g_part[blk*C + ch]           = s;
        g_part[256*128 + blk*C + ch] = q;
    }
}

__global__ void finalize_stats_kernel(int C) {
    int c = threadIdx.x;
    if (c >= C) return;
    double s = 0.0, q = 0.0;
    for (int b2 = 0; b2 < 256; b2++) {
        s += g_part[b2*C + c];
        q += g_part[256*128 + b2*C + c];
    }
    double n = (double)M_TOTAL;
    double m = s / n;
    double var = q / n - m*m;
    g_mu[c] = (float)m;
    g_rs[c] = (float)(1.0 / sqrt(var + 1e-5));
}

// 6) BN+ReLU on y2 then max over nsample; write new_points [B,128,NP]
__global__ void maxpool_kernel(const float* __restrict__ gam,
                               const float* __restrict__ bet,
                               float* __restrict__ out) {
    __shared__ float sh[32*129];
    int b = blockIdx.x, st = blockIdx.y;
    int c = threadIdx.x;                   // 128 threads
    float mu = g_mu[c], rs = g_rs[c], ga = gam[c], be = bet[c];
    int s0 = st * 32;
    for (int sl = 0; sl < 32; ++sl) {
        size_t base = ((size_t)((b*NP + s0 + sl)*NS)) * 128;
        float mx = 0.0f;                   // relu outputs are >= 0
        #pragma unroll 4
        for (int k = 0; k < NS; k++) {
            float v = g_y2[base + (size_t)k*128 + c];
            v = ((v - mu) * rs) * ga + be;
            mx = fmaxf(mx, fmaxf(v, 0.0f));
        }
        sh[sl*129 + c] = mx;
    }
    __syncthreads();
    float* ob = out + (size_t)BB*3*NP + (size_t)b*128*NP + s0;
    for (int i = c; i < 32*128; i += 128) {
        int ch = i >> 5, j = i & 31;
        ob[(size_t)ch*NP + j] = sh[j*129 + ch];
    }
}

// ---------------------------------------------------------------------------
extern "C" void kernel_launch(void* const* d_in, const int* in_sizes, int n_in,
                              void* d_out, int out_size) {
    const float* xyz = (const float*)d_in[0];
    const float* pts = (const float*)d_in[1];
    const float* w0  = (const float*)d_in[2];
    const float* b0  = (const float*)d_in[3];
    const float* g0  = (const float*)d_in[4];
    const float* be0 = (const float*)d_in[5];
    const float* w1  = (const float*)d_in[6];
    const float* b1  = (const float*)d_in[7];
    const float* g1  = (const float*)d_in[8];
    const float* be1 = (const float*)d_in[9];
    const float* w2  = (const float*)d_in[10];
    const float* b2  = (const float*)d_in[11];
    const float* g2  = (const float*)d_in[12];
    const float* be2 = (const float*)d_in[13];
    float* out = (float*)d_out;

    const int smem0 = (67*64 + 256*69) * 4;   // 87808 B
    const int smem1 = (64*64 + 256*65) * 4;   // 82944 B
    cudaFuncSetAttribute(gemm0_kernel,    cudaFuncAttributeMaxDynamicSharedMemorySize, smem0);
    cudaFuncSetAttribute(gemm_mid_kernel, cudaFuncAttributeMaxDynamicSharedMemorySize, smem1);

    transpose_pts_kernel<<<dim3(128, 2, 16), dim3(32, 8)>>>(pts);
    fps_kernel<<<16, 512>>>(xyz, out);
    ball_query_kernel<<<2048, 256>>>(xyz);

    // layer 0: concat-gather GEMM (no BN on input)
    gemm0_kernel<<<2048, 256, smem0>>>(xyz, w0, b0);
    reduce_stats_kernel<<<256, 256>>>(0, 64);
    finalize_stats_kernel<<<1, 128>>>(64);

    // layer 1: BN0+ReLU fused into A-load -> y1
    gemm_mid_kernel<<<dim3(2048, 1), 256, smem1>>>(w1, 64, b1, g0, be0, 1);
    reduce_stats_kernel<<<256, 256>>>(1, 64);
    finalize_stats_kernel<<<1, 128>>>(64);

    // layer 2: BN1+ReLU fused into A-load -> y2 (128 cols)
    gemm_mid_kernel<<<dim3(2048, 2), 256, smem1>>>(w2, 128, b2, g1, be1, 2);
    reduce_stats_kernel<<<256, 256>>>(2, 128);
    finalize_stats_kernel<<<1, 128>>>(128);

    // BN2+ReLU+maxpool -> out
    maxpool_kernel<<<dim3(16, 32), 128>>>(g2, be2, out);
}

// round 3
// speedup vs baseline: 1.1185x; 1.1185x over previous
#include <cuda_runtime.h>
#include <math.h>
#include <stdint.h>

#define BB 16
#define NN 4096
#define NP 1024
#define NS 32
#define DIN 64
#define M_TOTAL (BB*NP*NS)   /* 524288 rows of the flattened (b,s,k) axis */

// ---------------------------------------------------------------------------
// Scratch (device globals; no allocation allowed)
// ---------------------------------------------------------------------------
__device__ float  g_pts_t[BB*NN*DIN];        // points transposed [B,N,64]   16 MB
__device__ float  g_new_xyz[BB*NP*3];        // sampled centroids [B,NP,3]
__device__ int    g_idx[M_TOTAL];            // ball-query indices [B,NP,NS]
__device__ float  g_y0[M_TOTAL*64];          // layer0 pre-BN output  134 MB
__device__ float  g_y1[M_TOTAL*64];          // layer1 pre-BN output  134 MB
__device__ float  g_y2[(size_t)M_TOTAL*128]; // layer2 pre-BN output  268 MB
__device__ float  g_pS[2048*128];            // per-block channel sums
__device__ float  g_pQ[2048*128];            // per-block channel sumsq
__device__ float  g_mu[128];
__device__ float  g_rs[128];

// ---------------------------------------------------------------------------
// 0) transpose points [B,64,N] -> [B,N,64]
// ---------------------------------------------------------------------------
__global__ void transpose_pts_kernel(const float* __restrict__ pts) {
    __shared__ float tile[32][33];
    int b  = blockIdx.z;
    int n0 = blockIdx.x * 32;
    int c0 = blockIdx.y * 32;
    int tx = threadIdx.x, ty = threadIdx.y;   // 32 x 8
    const float* pb = pts + (size_t)b*DIN*NN;
    #pragma unroll
    for (int i = ty; i < 32; i += 8)
        tile[i][tx] = pb[(size_t)(c0+i)*NN + n0 + tx];
    __syncthreads();
    float* ob = g_pts_t + (size_t)b*NN*DIN;
    #pragma unroll
    for (int i = ty; i < 32; i += 8)
        ob[(size_t)(n0+i)*DIN + c0 + tx] = tile[tx][i];
}

// ---------------------------------------------------------------------------
// 1) Farthest point sampling. One block per batch, 512 threads, 8 pts/thread.
// ---------------------------------------------------------------------------
__global__ void fps_kernel(const float* __restrict__ xyz, float* __restrict__ out) {
    int b = blockIdx.x, tid = threadIdx.x;     // 512 threads
    const float* xb = xyz + (size_t)b*3*NN;
    float px[8], py[8], pz[8], dd[8];
    #pragma unroll
    for (int i = 0; i < 8; i++) {
        int n = tid + i*512;
        px[i] = xb[n]; py[i] = xb[NN+n]; pz[i] = xb[2*NN+n];
        dd[i] = 1e10f;
    }
    __shared__ int      s_fps[NP];
    __shared__ unsigned s_wv[16];
    __shared__ int      s_wi[16];
    __shared__ int      s_far;
    if (tid == 0) s_fps[0] = 0;
    int far = 0;
    for (int it = 1; it < NP; ++it) {
        float cx = __ldg(xb + far);
        float cy = __ldg(xb + NN + far);
        float cz = __ldg(xb + 2*NN + far);
        unsigned bv = 0u, bi = 0x7fffffffu;
        #pragma unroll
        for (int i = 0; i < 8; i++) {
            float dx = __fsub_rn(px[i], cx);
            float dy = __fsub_rn(py[i], cy);
            float dz = __fsub_rn(pz[i], cz);
            float d  = __fadd_rn(__fadd_rn(__fmul_rn(dx,dx), __fmul_rn(dy,dy)),
                                 __fmul_rn(dz,dz));
            dd[i] = fminf(dd[i], d);
            unsigned vb = __float_as_uint(dd[i]);
            if (vb > bv) { bv = vb; bi = (unsigned)(tid + i*512); }
        }
        unsigned wmax = __reduce_max_sync(0xffffffffu, bv);
        unsigned cand = (bv == wmax) ? bi : 0x7fffffffu;
        unsigned wi   = __reduce_min_sync(0xffffffffu, cand);
        if ((tid & 31) == 0) { s_wv[tid >> 5] = wmax; s_wi[tid >> 5] = (int)wi; }
        __syncthreads();
        if (tid < 32) {
            unsigned v  = (tid < 16) ? s_wv[tid] : 0u;
            unsigned ix = (tid < 16) ? (unsigned)s_wi[tid] : 0x7fffffffu;
            unsigned m2 = __reduce_max_sync(0xffffffffu, v);
            unsigned c2 = (v == m2) ? ix : 0x7fffffffu;
            unsigned gi = __reduce_min_sync(0xffffffffu, c2);
            if (tid == 0) { s_far = (int)gi; s_fps[it] = (int)gi; }
        }
        __syncthreads();
        far = s_far;
    }
    for (int s = tid; s < NP; s += 512) {
        int j = s_fps[s];
        float x = xb[j], y = xb[NN+j], z = xb[2*NN+j];
        out[(size_t)b*3*NP + s]        = x;
        out[(size_t)b*3*NP + NP + s]   = y;
        out[(size_t)b*3*NP + 2*NP + s] = z;
        float* nx = g_new_xyz + ((size_t)b*NP + s)*3;
        nx[0] = x; nx[1] = y; nx[2] = z;
    }
}

// ---------------------------------------------------------------------------
// 2) Ball query: one warp per centroid.
// ---------------------------------------------------------------------------
__global__ void ball_query_kernel(const float* __restrict__ xyz) {
    int gt   = blockIdx.x * blockDim.x + threadIdx.x;
    int warp = gt >> 5;
    int lane = gt & 31;
    if (warp >= BB*NP) return;
    int b = warp >> 10;
    const float* xb = xyz + (size_t)b*3*NN;
    const float* nx = g_new_xyz + (size_t)warp*3;
    float cx = nx[0], cy = nx[1], cz = nx[2];
    float ssrc = __fadd_rn(__fadd_rn(__fmul_rn(cx,cx), __fmul_rn(cy,cy)), __fmul_rn(cz,cz));
    const float R2 = 0.04f;
    int cnt = 0, first = -1;
    int* op = g_idx + (size_t)warp*NS;
    for (int j0 = 0; j0 < NN && cnt < NS; j0 += 32) {
        int j = j0 + lane;
        float x = xb[j], y = xb[NN+j], z = xb[2*NN+j];
        float sdst = __fadd_rn(__fadd_rn(__fmul_rn(x,x), __fmul_rn(y,y)), __fmul_rn(z,z));
        float dot  = __fadd_rn(__fadd_rn(__fmul_rn(cx,x), __fmul_rn(cy,y)), __fmul_rn(cz,z));
        float d = __fadd_rn(__fadd_rn(__fmul_rn(-2.0f, dot), ssrc), sdst);
        bool in = !(d > R2);
        unsigned m = __ballot_sync(0xffffffffu, in);
        if (first < 0 && m) first = j0 + __ffs(m) - 1;
        if (in) {
            int slot = cnt + __popc(m & ((1u << lane) - 1u));
            if (slot < NS) op[slot] = j;
        }
        cnt += __popc(m);
    }
    if (cnt < NS) {
        if (first < 0) first = NN - 1;
        for (int slot = cnt + lane; slot < NS; slot += 32) op[slot] = first;
    }
}

// ---------------------------------------------------------------------------
// GEMM core: software-pipelined, conflict-free W (Wlo/Whi 128B rows).
// As row-major pitch P; Wlo/Whi are [K][32] float (= [K][8] float4).
// ---------------------------------------------------------------------------
#define FMA8(a, w0, w1, accrow) \
    accrow[0] += a*w0.x; accrow[1] += a*w0.y; accrow[2] += a*w0.z; accrow[3] += a*w0.w; \
    accrow[4] += a*w1.x; accrow[5] += a*w1.y; accrow[6] += a*w1.z; accrow[7] += a*w1.w;

template<int K, int P>
__device__ __forceinline__ void gemm_pipe(const float* __restrict__ As,
                                          const float* __restrict__ Wlo,
                                          const float* __restrict__ Whi,
                                          int rg, int cg, float acc[8][8]) {
    const float* ap  = As + rg*8*P;
    const float* wlp = Wlo + cg*4;
    const float* whp = Whi + cg*4;
    float a[8]; float4 w0, w1;
    #pragma unroll
    for (int i = 0; i < 8; i++) a[i] = ap[i*P];
    w0 = *(const float4*)(wlp);
    w1 = *(const float4*)(whp);
    #pragma unroll 4
    for (int k = 0; k < K-1; ++k) {
        float an[8]; float4 w0n, w1n;
        #pragma unroll
        for (int i = 0; i < 8; i++) an[i] = ap[i*P + k + 1];
        w0n = *(const float4*)(wlp + (k+1)*32);
        w1n = *(const float4*)(whp + (k+1)*32);
        #pragma unroll
        for (int i = 0; i < 8; i++) { FMA8(a[i], w0, w1, acc[i]); }
        #pragma unroll
        for (int i = 0; i < 8; i++) a[i] = an[i];
        w0 = w0n; w1 = w1n;
    }
    #pragma unroll
    for (int i = 0; i < 8; i++) { FMA8(a[i], w0, w1, acc[i]); }
}

// Fill Wlo/Whi from a global row-major weight [K][64] slice.
__device__ __forceinline__ void fill_w(float* Wlo, float* Whi,
                                       const float* __restrict__ w, int ldw,
                                       int c0, int K, int tid) {
    for (int i = tid; i < K*64; i += 256) {
        int k = i >> 6, c = i & 63;
        float v = w[k*ldw + c0 + c];
        int cg = c >> 3, t = c & 7;
        if (t < 4) Wlo[k*32 + cg*4 + t]     = v;
        else       Whi[k*32 + cg*4 + t - 4] = v;
    }
}

// Epilogue: store vals, accumulate per-block channel sum/sumsq partials.
// Reuses the As region (>= 2*64*33 floats) for the cross-rg reduction.
__device__ __forceinline__ void epilogue_store_stats(
    float vals[8][8], float* __restrict__ yout, size_t row0, int ldo, int cbase,
    float* As, int rg, int cg, int part_idx /* bx*Cl + c0 */) {
    float s8[8], q8[8];
    #pragma unroll
    for (int j = 0; j < 8; j++) { s8[j] = 0.0f; q8[j] = 0.0f; }
    #pragma unroll
    for (int i = 0; i < 8; i++) {
        float4 v0 = make_float4(vals[i][0], vals[i][1], vals[i][2], vals[i][3]);
        float4 v1 = make_float4(vals[i][4], vals[i][5], vals[i][6], vals[i][7]);
        *(float4*)&yout[(row0 + i)*(size_t)ldo + cbase]     = v0;
        *(float4*)&yout[(row0 + i)*(size_t)ldo + cbase + 4] = v1;
        #pragma unroll
        for (int j = 0; j < 8; j++) { s8[j] += vals[i][j]; q8[j] += vals[i][j]*vals[i][j]; }
    }
    __syncthreads();                 // everyone done reading As
    float* rS = As;                  // [64][33]
    float* rQ = As + 64*33;          // [64][33]
    #pragma unroll
    for (int j = 0; j < 8; j++) {
        rS[(cg*8 + j)*33 + rg] = s8[j];
        rQ[(cg*8 + j)*33 + rg] = q8[j];
    }
    __syncthreads();
    int tid = rg*8 + cg;             // == threadIdx.x
    if (tid < 64) {
        float s = 0.0f, q = 0.0f;
        #pragma unroll 8
        for (int r = 0; r < 32; r++) { s += rS[tid*33 + r]; q += rQ[tid*33 + r]; }
        g_pS[part_idx + tid] = s;
        g_pQ[part_idx + tid] = q;
    }
}

// 3) Layer 0: gather (grouped_xyz | grouped_pts) on the fly, K=67 -> 64
__global__ void __launch_bounds__(256, 2)
gemm0_kernel(const float* __restrict__ xyz, const float* __restrict__ w,
             const float* __restrict__ bias) {
    extern __shared__ float sm[];
    float* Wlo = sm;               // 67*32
    float* Whi = sm + 67*32;       // 67*32
    float* As  = sm + 67*64;       // 256*69
    __shared__ int sj[256];
    int tid = threadIdx.x;
    int m0  = blockIdx.x * 256;
    fill_w(Wlo, Whi, w, 64, 0, 67, tid);
    sj[tid] = g_idx[m0 + tid];
    __syncthreads();
    int b = m0 >> 15;
    const float* ptb = g_pts_t + (size_t)b*NN*DIN;
    for (int i = tid; i < 256*64; i += 256) {
        int r = i >> 6, c = i & 63;
        As[r*69 + 3 + c] = ptb[(size_t)sj[r]*64 + c];
    }
    const float* xb = xyz + (size_t)b*3*NN;
    for (int i = tid; i < 256*3; i += 256) {
        int r = i / 3, d = i - r*3;
        As[r*69 + d] = __fsub_rn(xb[d*NN + sj[r]], g_new_xyz[((m0+r) >> 5)*3 + d]);
    }
    __syncthreads();
    int rg = tid >> 3, cg = tid & 7;
    float acc[8][8];
    #pragma unroll
    for (int i = 0; i < 8; i++)
        #pragma unroll
        for (int j = 0; j < 8; j++) acc[i][j] = 0.0f;
    gemm_pipe<67, 69>(As, Wlo, Whi, rg, cg, acc);
    float bb[8];
    #pragma unroll
    for (int j = 0; j < 8; j++) bb[j] = bias[cg*8 + j];
    #pragma unroll
    for (int i = 0; i < 8; i++)
        #pragma unroll
        for (int j = 0; j < 8; j++) acc[i][j] += bb[j];
    epilogue_store_stats(acc, g_y0, (size_t)(m0 + rg*8), 64, cg*8,
                         As, rg, cg, blockIdx.x*64);
}

// 4) Layers 1/2: BN(prev stats)+ReLU fused into A-load, K=64 -> 64-col slice.
__global__ void __launch_bounds__(256, 2)
gemm_mid_kernel(const float* __restrict__ w, int ldw,
                const float* __restrict__ bias,
                const float* __restrict__ gam, const float* __restrict__ bet,
                int layer) {
    extern __shared__ float sm[];
    float* Wlo = sm;               // 64*32
    float* Whi = sm + 64*32;       // 64*32
    float* As  = sm + 64*64;       // 256*65
    __shared__ float s_mu[64], s_rs[64], s_g[64], s_b[64];
    const float* yin  = (layer == 1) ? g_y0 : g_y1;
    float*       yout = (layer == 1) ? g_y1 : g_y2;
    int ldo = (layer == 1) ? 64 : 128;
    int Cl  = (layer == 1) ? 64 : 128;
    int tid = threadIdx.x;
    int m0  = blockIdx.x * 256;
    int c0  = blockIdx.y * 64;
    if (tid < 64) { s_mu[tid] = g_mu[tid]; s_rs[tid] = g_rs[tid];
                    s_g[tid]  = gam[tid];  s_b[tid]  = bet[tid]; }
    fill_w(Wlo, Whi, w, ldw, c0, 64, tid);
    __syncthreads();
    for (int i = tid; i < 256*64; i += 256) {
        int r = i >> 6, k = i & 63;
        float v = yin[(size_t)(m0 + r)*64 + k];
        v = ((v - s_mu[k]) * s_rs[k]) * s_g[k] + s_b[k];
        As[r*65 + k] = fmaxf(v, 0.0f);
    }
    __syncthreads();
    int rg = tid >> 3, cg = tid & 7;
    float acc[8][8];
    #pragma unroll
    for (int i = 0; i < 8; i++)
        #pragma unroll
        for (int j = 0; j < 8; j++) acc[i][j] = 0.0f;
    gemm_pipe<64, 65>(As, Wlo, Whi, rg, cg, acc);
    float bb[8];
    #pragma unroll
    for (int j = 0; j < 8; j++) bb[j] = bias[c0 + cg*8 + j];
    #pragma unroll
    for (int i = 0; i < 8; i++)
        #pragma unroll
        for (int j = 0; j < 8; j++) acc[i][j] += bb[j];
    epilogue_store_stats(acc, yout, (size_t)(m0 + rg*8), ldo, c0 + cg*8,
                         As, rg, cg, blockIdx.x*Cl + c0);
}

// 5) finalize: double-precision reduce of 2048 float partials per channel
__global__ void finalize_stats_kernel(int C) {
    __shared__ double shs[512], shq[512];
    int tid = threadIdx.x;                    // 512 threads
    int c   = tid & (C - 1);
    int rep = tid / C;
    int nrep = 512 / C;
    int per = 2048 / nrep;
    double s = 0.0, q = 0.0;
    for (int b = rep*per; b < (rep+1)*per; b++) {
        s += (double)g_pS[b*C + c];
        q += (double)g_pQ[b*C + c];
    }
    shs[tid] = s; shq[tid] = q;
    __syncthreads();
    if (rep == 0) {
        for (int r = 1; r < nrep; r++) { s += shs[r*C + c]; q += shq[r*C + c]; }
        double n = (double)M_TOTAL;
        double m = s / n;
        double var = q / n - m*m;
        g_mu[c] = (float)m;
        g_rs[c] = (float)(1.0 / sqrt(var + 1e-5));
    }
}

// 6) BN+ReLU on y2 then max over nsample; write new_points [B,128,NP]
__global__ void maxpool_kernel(const float* __restrict__ gam,
                               const float* __restrict__ bet,
                               float* __restrict__ out) {
    __shared__ float sh[32*129];
    int b = blockIdx.x, st = blockIdx.y;
    int c = threadIdx.x;                   // 128 threads
    float mu = g_mu[c], rs = g_rs[c], ga = gam[c], be = bet[c];
    int s0 = st * 32;
    for (int sl = 0; sl < 32; ++sl) {
        size_t base = ((size_t)((b*NP + s0 + sl)*NS)) * 128;
        float mx = 0.0f;
        #pragma unroll 4
        for (int k = 0; k < NS; k++) {
            float v = g_y2[base + (size_t)k*128 + c];
            v = ((v - mu) * rs) * ga + be;
            mx = fmaxf(mx, fmaxf(v, 0.0f));
        }
        sh[sl*129 + c] = mx;
    }
    __syncthreads();
    float* ob = out + (size_t)BB*3*NP + (size_t)b*128*NP + s0;
    for (int i = c; i < 32*128; i += 128) {
        int ch = i >> 5, j = i & 31;
        ob[(size_t)ch*NP + j] = sh[j*129 + ch];
    }
}

// ---------------------------------------------------------------------------
extern "C" void kernel_launch(void* const* d_in, const int* in_sizes, int n_in,
                              void* d_out, int out_size) {
    const float* xyz = (const float*)d_in[0];
    const float* pts = (const float*)d_in[1];
    const float* w0  = (const float*)d_in[2];
    const float* b0  = (const float*)d_in[3];
    const float* g0  = (const float*)d_in[4];
    const float* be0 = (const float*)d_in[5];
    const float* w1  = (const float*)d_in[6];
    const float* b1  = (const float*)d_in[7];
    const float* g1  = (const float*)d_in[8];
    const float* be1 = (const float*)d_in[9];
    const float* w2  = (const float*)d_in[10];
    const float* b2  = (const float*)d_in[11];
    const float* g2  = (const float*)d_in[12];
    const float* be2 = (const float*)d_in[13];
    float* out = (float*)d_out;

    const int smem0 = (67*64 + 256*69) * 4;   // 87808 B
    const int smem1 = (64*64 + 256*65) * 4;   // 82944 B
    cudaFuncSetAttribute(gemm0_kernel,    cudaFuncAttributeMaxDynamicSharedMemorySize, smem0);
    cudaFuncSetAttribute(gemm_mid_kernel, cudaFuncAttributeMaxDynamicSharedMemorySize, smem1);

    transpose_pts_kernel<<<dim3(128, 2, 16), dim3(32, 8)>>>(pts);
    fps_kernel<<<16, 512>>>(xyz, out);
    ball_query_kernel<<<2048, 256>>>(xyz);

    // layer 0: concat-gather GEMM (stats fused into epilogue)
    gemm0_kernel<<<2048, 256, smem0>>>(xyz, w0, b0);
    finalize_stats_kernel<<<1, 512>>>(64);

    // layer 1: BN0+ReLU fused into A-load -> y1
    gemm_mid_kernel<<<dim3(2048, 1), 256, smem1>>>(w1, 64, b1, g0, be0, 1);
    finalize_stats_kernel<<<1, 512>>>(64);

    // layer 2: BN1+ReLU fused into A-load -> y2 (128 cols)
    gemm_mid_kernel<<<dim3(2048, 2), 256, smem1>>>(w2, 128, b2, g1, be1, 2);
    finalize_stats_kernel<<<1, 512>>>(128);

    // BN2+ReLU+maxpool -> out
    maxpool_kernel<<<dim3(16, 32), 128>>>(g2, be2, out);
}

// round 4
// speedup vs baseline: 1.3447x; 1.2023x over previous
#include <cuda_runtime.h>
#include <math.h>
#include <stdint.h>

#define BB 16
#define NN 4096
#define NP 1024
#define NS 32
#define M_TOTAL (BB*NP*NS)   /* 524288 */
#define PITCH 132            /* k-major A pitch (128 rows + pad) */

// ---------------------------------------------------------------------------
// Scratch
// ---------------------------------------------------------------------------
__device__ float g_P[(size_t)BB*NN*64];       // pts-part of layer0   16.8 MB
__device__ float g_new_xyz[BB*NP*3];
__device__ int   g_idx[M_TOTAL];
__device__ float g_y1[(size_t)M_TOTAL*64];    // layer1 pre-BN       134 MB
__device__ float g_gmax[(size_t)BB*NP*128];   // per-group raw max     8 MB
__device__ float g_gmin[(size_t)BB*NP*128];   // per-group raw min     8 MB
__device__ float g_pS[4096*128];
__device__ float g_pQ[4096*128];
__device__ float g_mu[128];
__device__ float g_rs[128];

// ---------------------------------------------------------------------------
// 1) Farthest point sampling (unchanged)
// ---------------------------------------------------------------------------
__global__ void fps_kernel(const float* __restrict__ xyz, float* __restrict__ out) {
    int b = blockIdx.x, tid = threadIdx.x;     // 512 threads
    const float* xb = xyz + (size_t)b*3*NN;
    float px[8], py[8], pz[8], dd[8];
    #pragma unroll
    for (int i = 0; i < 8; i++) {
        int n = tid + i*512;
        px[i] = xb[n]; py[i] = xb[NN+n]; pz[i] = xb[2*NN+n];
        dd[i] = 1e10f;
    }
    __shared__ int      s_fps[NP];
    __shared__ unsigned s_wv[16];
    __shared__ int      s_wi[16];
    __shared__ int      s_far;
    if (tid == 0) s_fps[0] = 0;
    int far = 0;
    for (int it = 1; it < NP; ++it) {
        float cx = __ldg(xb + far);
        float cy = __ldg(xb + NN + far);
        float cz = __ldg(xb + 2*NN + far);
        unsigned bv = 0u, bi = 0x7fffffffu;
        #pragma unroll
        for (int i = 0; i < 8; i++) {
            float dx = __fsub_rn(px[i], cx);
            float dy = __fsub_rn(py[i], cy);
            float dz = __fsub_rn(pz[i], cz);
            float d  = __fadd_rn(__fadd_rn(__fmul_rn(dx,dx), __fmul_rn(dy,dy)),
                                 __fmul_rn(dz,dz));
            dd[i] = fminf(dd[i], d);
            unsigned vb = __float_as_uint(dd[i]);
            if (vb > bv) { bv = vb; bi = (unsigned)(tid + i*512); }
        }
        unsigned wmax = __reduce_max_sync(0xffffffffu, bv);
        unsigned cand = (bv == wmax) ? bi : 0x7fffffffu;
        unsigned wi   = __reduce_min_sync(0xffffffffu, cand);
        if ((tid & 31) == 0) { s_wv[tid >> 5] = wmax; s_wi[tid >> 5] = (int)wi; }
        __syncthreads();
        if (tid < 32) {
            unsigned v  = (tid < 16) ? s_wv[tid] : 0u;
            unsigned ix = (tid < 16) ? (unsigned)s_wi[tid] : 0x7fffffffu;
            unsigned m2 = __reduce_max_sync(0xffffffffu, v);
            unsigned c2 = (v == m2) ? ix : 0x7fffffffu;
            unsigned gi = __reduce_min_sync(0xffffffffu, c2);
            if (tid == 0) { s_far = (int)gi; s_fps[it] = (int)gi; }
        }
        __syncthreads();
        far = s_far;
    }
    for (int s = tid; s < NP; s += 512) {
        int j = s_fps[s];
        float x = xb[j], y = xb[NN+j], z = xb[2*NN+j];
        out[(size_t)b*3*NP + s]        = x;
        out[(size_t)b*3*NP + NP + s]   = y;
        out[(size_t)b*3*NP + 2*NP + s] = z;
        float* nx = g_new_xyz + ((size_t)b*NP + s)*3;
        nx[0] = x; nx[1] = y; nx[2] = z;
    }
}

// ---------------------------------------------------------------------------
// 2) Ball query (unchanged)
// ---------------------------------------------------------------------------
__global__ void ball_query_kernel(const float* __restrict__ xyz) {
    int gt   = blockIdx.x * blockDim.x + threadIdx.x;
    int warp = gt >> 5;
    int lane = gt & 31;
    if (warp >= BB*NP) return;
    int b = warp >> 10;
    const float* xb = xyz + (size_t)b*3*NN;
    const float* nx = g_new_xyz + (size_t)warp*3;
    float cx = nx[0], cy = nx[1], cz = nx[2];
    float ssrc = __fadd_rn(__fadd_rn(__fmul_rn(cx,cx), __fmul_rn(cy,cy)), __fmul_rn(cz,cz));
    const float R2 = 0.04f;
    int cnt = 0, first = -1;
    int* op = g_idx + (size_t)warp*NS;
    for (int j0 = 0; j0 < NN && cnt < NS; j0 += 32) {
        int j = j0 + lane;
        float x = xb[j], y = xb[NN+j], z = xb[2*NN+j];
        float sdst = __fadd_rn(__fadd_rn(__fmul_rn(x,x), __fmul_rn(y,y)), __fmul_rn(z,z));
        float dot  = __fadd_rn(__fadd_rn(__fmul_rn(cx,x), __fmul_rn(cy,y)), __fmul_rn(cz,z));
        float d = __fadd_rn(__fadd_rn(__fmul_rn(-2.0f, dot), ssrc), sdst);
        bool in = !(d > R2);
        unsigned m = __ballot_sync(0xffffffffu, in);
        if (first < 0 && m) first = j0 + __ffs(m) - 1;
        if (in) {
            int slot = cnt + __popc(m & ((1u << lane) - 1u));
            if (slot < NS) op[slot] = j;
        }
        cnt += __popc(m);
    }
    if (cnt < NS) {
        if (first < 0) first = NN - 1;
        for (int slot = cnt + lane; slot < NS; slot += 32) op[slot] = first;
    }
}

// ---------------------------------------------------------------------------
// GEMM helpers: 128x64 tile, 256 threads, 4x8 register tile, k-major A.
// ---------------------------------------------------------------------------
#define FMA8(a, w0, w1, accrow) \
    accrow[0] += a*w0.x; accrow[1] += a*w0.y; accrow[2] += a*w0.z; accrow[3] += a*w0.w; \
    accrow[4] += a*w1.x; accrow[5] += a*w1.y; accrow[6] += a*w1.z; accrow[7] += a*w1.w;

__device__ __forceinline__ void gemm_kloop(const float* __restrict__ As,
                                           const float* __restrict__ Wlo,
                                           const float* __restrict__ Whi,
                                           int rg, int cg, float acc[4][8]) {
    const float* ap = As + rg*4;
    const float* wl = Wlo + cg*4;
    const float* wh = Whi + cg*4;
    #pragma unroll 8
    for (int k = 0; k < 64; ++k) {
        float4 a  = *(const float4*)(ap + k*PITCH);
        float4 w0 = *(const float4*)(wl + k*32);
        float4 w1 = *(const float4*)(wh + k*32);
        FMA8(a.x, w0, w1, acc[0]);
        FMA8(a.y, w0, w1, acc[1]);
        FMA8(a.z, w0, w1, acc[2]);
        FMA8(a.w, w0, w1, acc[3]);
    }
}

// W fill: global row-major [K][ldw] slice c0..c0+63 -> Wlo/Whi [K][32]
__device__ __forceinline__ void fill_w64(float* Wlo, float* Whi,
                                         const float* __restrict__ w, int ldw,
                                         int c0, int tid) {
    for (int i = tid; i < 64*64; i += 256) {
        int k = i >> 6, c = i & 63;
        float v = w[k*ldw + c0 + c];
        int cgg = c >> 3, t = c & 7;
        if (t < 4) Wlo[k*32 + cgg*4 + t]     = v;
        else       Whi[k*32 + cgg*4 + t - 4] = v;
    }
}

// ---------------------------------------------------------------------------
// 3) P = pts^T @ W0[3:67] + b0   (per batch: 4096x64 @ 64x64)
// ---------------------------------------------------------------------------
__global__ void __launch_bounds__(256, 4)
pgemm_kernel(const float* __restrict__ pts, const float* __restrict__ w0,
             const float* __restrict__ b0) {
    extern __shared__ __align__(16) float sm[];
    float* As  = sm;                 // [64][PITCH]
    float* Wlo = sm + 64*PITCH;
    float* Whi = Wlo + 64*32;
    int tid = threadIdx.x;
    int bx  = blockIdx.x;
    int b   = bx >> 5;
    int n0  = (bx & 31) * 128;
    fill_w64(Wlo, Whi, w0 + 3*64, 64, 0, tid);
    const float* pb = pts + (size_t)b*64*NN;
    for (int i = tid; i < 64*128; i += 256) {
        int c = i >> 7, r = i & 127;
        As[c*PITCH + r] = pb[(size_t)c*NN + n0 + r];
    }
    __syncthreads();
    int rg = tid >> 3, cg = tid & 7;
    float acc[4][8];
    #pragma unroll
    for (int i = 0; i < 4; i++)
        #pragma unroll
        for (int j = 0; j < 8; j++) acc[i][j] = 0.0f;
    gemm_kloop(As, Wlo, Whi, rg, cg, acc);
    float bb[8];
    #pragma unroll
    for (int j = 0; j < 8; j++) bb[j] = b0[cg*8 + j];
    #pragma unroll
    for (int i = 0; i < 4; i++) {
        size_t row = (size_t)b*NN + n0 + rg*4 + i;
        float4 v0 = make_float4(acc[i][0]+bb[0], acc[i][1]+bb[1], acc[i][2]+bb[2], acc[i][3]+bb[3]);
        float4 v1 = make_float4(acc[i][4]+bb[4], acc[i][5]+bb[5], acc[i][6]+bb[6], acc[i][7]+bb[7]);
        *(float4*)&g_P[row*64 + cg*8]     = v0;
        *(float4*)&g_P[row*64 + cg*8 + 4] = v1;
    }
}

// ---------------------------------------------------------------------------
// 4) stats of y0 (never materialized): y0 = P[j] + dxyz . W0[0:3]
//    2048 blocks x 256 rows
// ---------------------------------------------------------------------------
__global__ void __launch_bounds__(256)
stats0_kernel(const float* __restrict__ xyz, const float* __restrict__ w0) {
    __shared__ float sdx[256], sdy[256], sdz[256];
    __shared__ int   sj[256];
    __shared__ __align__(16) float s_w0[192];
    __shared__ float redS[64*17], redQ[64*17];
    int tid = threadIdx.x;
    int m0  = blockIdx.x * 256;
    int b   = m0 >> 15;
    if (tid < 192) s_w0[tid] = w0[tid];
    {
        int r = tid;
        int j = g_idx[m0 + r];
        sj[r] = j;
        const float* xb = xyz + (size_t)b*3*NN;
        const float* nx = g_new_xyz + (size_t)((m0 + r) >> 5)*3;
        sdx[r] = __fsub_rn(xb[j],      nx[0]);
        sdy[r] = __fsub_rn(xb[NN+j],   nx[1]);
        sdz[r] = __fsub_rn(xb[2*NN+j], nx[2]);
    }
    __syncthreads();
    int q  = tid >> 4;     // 0..15 (float4 channel group)
    int rl = tid & 15;
    float4 wx = *(const float4*)(s_w0 + q*4);
    float4 wy = *(const float4*)(s_w0 + 64 + q*4);
    float4 wz = *(const float4*)(s_w0 + 128 + q*4);
    float sx=0,sy=0,sz=0,sw=0, qx=0,qy=0,qz=0,qw=0;
    const float* Pb = g_P + (size_t)b*NN*64;
    for (int n = 0; n < 16; n++) {
        int r = rl + n*16;
        float4 p = *(const float4*)(Pb + (size_t)sj[r]*64 + q*4);
        float dx = sdx[r], dy = sdy[r], dz = sdz[r];
        float yx = p.x + dx*wx.x + dy*wy.x + dz*wz.x;
        float yy = p.y + dx*wx.y + dy*wy.y + dz*wz.y;
        float yz = p.z + dx*wx.z + dy*wy.z + dz*wz.z;
        float yw = p.w + dx*wx.w + dy*wy.w + dz*wz.w;
        sx += yx; sy += yy; sz += yz; sw += yw;
        qx += yx*yx; qy += yy*yy; qz += yz*yz; qw += yw*yw;
    }
    redS[(4*q+0)*17 + rl] = sx; redQ[(4*q+0)*17 + rl] = qx;
    redS[(4*q+1)*17 + rl] = sy; redQ[(4*q+1)*17 + rl] = qy;
    redS[(4*q+2)*17 + rl] = sz; redQ[(4*q+2)*17 + rl] = qz;
    redS[(4*q+3)*17 + rl] = sw; redQ[(4*q+3)*17 + rl] = qw;
    __syncthreads();
    if (tid < 64) {
        float ss = 0.0f, sq = 0.0f;
        #pragma unroll
        for (int u = 0; u < 16; u++) { ss += redS[tid*17+u]; sq += redQ[tid*17+u]; }
        g_pS[blockIdx.x*64 + tid] = ss;
        g_pQ[blockIdx.x*64 + tid] = sq;
    }
}

// ---------------------------------------------------------------------------
// stats epilogue helper: per-block channel partials via As-region reuse.
// ---------------------------------------------------------------------------
__device__ __forceinline__ void stats_epilogue64(const float acc[4][8], float* red,
                                                 int rg, int cg, int tid, int part_base) {
    float s8[8], q8[8];
    #pragma unroll
    for (int j = 0; j < 8; j++) { s8[j] = 0.0f; q8[j] = 0.0f; }
    #pragma unroll
    for (int i = 0; i < 4; i++)
        #pragma unroll
        for (int j = 0; j < 8; j++) { s8[j] += acc[i][j]; q8[j] += acc[i][j]*acc[i][j]; }
    float* rS = red;            // [64][33]
    float* rQ = red + 64*33;
    #pragma unroll
    for (int j = 0; j < 8; j++) {
        rS[(cg*8 + j)*33 + rg] = s8[j];
        rQ[(cg*8 + j)*33 + rg] = q8[j];
    }
    __syncthreads();
    if (tid < 64) {
        float s = 0.0f, q = 0.0f;
        #pragma unroll 8
        for (int r = 0; r < 32; r++) { s += rS[tid*33 + r]; q += rQ[tid*33 + r]; }
        g_pS[part_base + tid] = s;
        g_pQ[part_base + tid] = q;
    }
}

// ---------------------------------------------------------------------------
// 5) layer1: A = BN0+ReLU(y0 recomputed on the fly), y1 = A @ W1 + b1
// ---------------------------------------------------------------------------
__global__ void __launch_bounds__(256, 4)
gemm1_kernel(const float* __restrict__ xyz, const float* __restrict__ w0,
             const float* __restrict__ w1, const float* __restrict__ b1,
             const float* __restrict__ gam0, const float* __restrict__ bet0) {
    extern __shared__ __align__(16) float sm[];
    float* As  = sm;
    float* Wlo = sm + 64*PITCH;
    float* Whi = Wlo + 64*32;
    __shared__ float sdx[128], sdy[128], sdz[128];
    __shared__ int   sj[128];
    __shared__ __align__(16) float s_w0[192];
    int tid = threadIdx.x;
    int m0  = blockIdx.x * 128;
    int b   = m0 >> 15;
    fill_w64(Wlo, Whi, w1, 64, 0, tid);
    if (tid < 192) s_w0[tid] = w0[tid];
    if (tid < 128) {
        int r = tid;
        int j = g_idx[m0 + r];
        sj[r] = j;
        const float* xb = xyz + (size_t)b*3*NN;
        const float* nx = g_new_xyz + (size_t)((m0 + r) >> 5)*3;
        sdx[r] = __fsub_rn(xb[j],      nx[0]);
        sdy[r] = __fsub_rn(xb[NN+j],   nx[1]);
        sdz[r] = __fsub_rn(xb[2*NN+j], nx[2]);
    }
    __syncthreads();
    {
        int q  = tid >> 4;    // channel group 0..15
        int rl = tid & 15;
        float4 wx = *(const float4*)(s_w0 + q*4);
        float4 wy = *(const float4*)(s_w0 + 64 + q*4);
        float4 wz = *(const float4*)(s_w0 + 128 + q*4);
        float sc[4], sh[4];
        #pragma unroll
        for (int t = 0; t < 4; t++) {
            int k = q*4 + t;
            sc[t] = g_rs[k]*gam0[k];
            sh[t] = bet0[k] - g_mu[k]*sc[t];
        }
        const float* Pb = g_P + (size_t)b*NN*64;
        for (int n = 0; n < 8; n++) {
            int r = rl + n*16;
            float4 p = *(const float4*)(Pb + (size_t)sj[r]*64 + q*4);
            float dx = sdx[r], dy = sdy[r], dz = sdz[r];
            float y0 = p.x + dx*wx.x + dy*wy.x + dz*wz.x;
            float y1v= p.y + dx*wx.y + dy*wy.y + dz*wz.y;
            float y2 = p.z + dx*wx.z + dy*wy.z + dz*wz.z;
            float y3 = p.w + dx*wx.w + dy*wy.w + dz*wz.w;
            As[(q*4+0)*PITCH + r] = fmaxf(y0*sc[0] + sh[0], 0.0f);
            As[(q*4+1)*PITCH + r] = fmaxf(y1v*sc[1] + sh[1], 0.0f);
            As[(q*4+2)*PITCH + r] = fmaxf(y2*sc[2] + sh[2], 0.0f);
            As[(q*4+3)*PITCH + r] = fmaxf(y3*sc[3] + sh[3], 0.0f);
        }
    }
    __syncthreads();
    int rg = tid >> 3, cg = tid & 7;
    float acc[4][8];
    #pragma unroll
    for (int i = 0; i < 4; i++)
        #pragma unroll
        for (int j = 0; j < 8; j++) acc[i][j] = 0.0f;
    gemm_kloop(As, Wlo, Whi, rg, cg, acc);
    float bb[8];
    #pragma unroll
    for (int j = 0; j < 8; j++) bb[j] = b1[cg*8 + j];
    #pragma unroll
    for (int i = 0; i < 4; i++)
        #pragma unroll
        for (int j = 0; j < 8; j++) acc[i][j] += bb[j];
    #pragma unroll
    for (int i = 0; i < 4; i++) {
        size_t row = (size_t)(m0 + rg*4 + i);
        float4 v0 = make_float4(acc[i][0], acc[i][1], acc[i][2], acc[i][3]);
        float4 v1 = make_float4(acc[i][4], acc[i][5], acc[i][6], acc[i][7]);
        *(float4*)&g_y1[row*64 + cg*8]     = v0;
        *(float4*)&g_y1[row*64 + cg*8 + 4] = v1;
    }
    __syncthreads();
    stats_epilogue64(acc, As, rg, cg, tid, blockIdx.x*64);
}

// ---------------------------------------------------------------------------
// 6) layer2: A = BN1+ReLU(y1), acc = A @ W2[:,c0:c0+64] + b2; epilogue:
//    stats partials + per-group (32-row) raw max/min -> g_gmax/g_gmin.
// ---------------------------------------------------------------------------
__global__ void __launch_bounds__(256, 4)
gemm2_kernel(const float* __restrict__ w2, const float* __restrict__ b2,
             const float* __restrict__ gam1, const float* __restrict__ bet1) {
    extern __shared__ __align__(16) float sm[];
    float* As  = sm;
    float* Wlo = sm + 64*PITCH;
    float* Whi = Wlo + 64*32;
    int tid = threadIdx.x;
    int m0  = blockIdx.x * 128;
    int c0  = blockIdx.y * 64;
    fill_w64(Wlo, Whi, w2, 128, c0, tid);
    {
        int q  = tid >> 4;
        int rl = tid & 15;
        float sc[4], sh[4];
        #pragma unroll
        for (int t = 0; t < 4; t++) {
            int k = q*4 + t;
            sc[t] = g_rs[k]*gam1[k];
            sh[t] = bet1[k] - g_mu[k]*sc[t];
        }
        for (int n = 0; n < 8; n++) {
            int r = rl + n*16;
            float4 p = *(const float4*)(g_y1 + (size_t)(m0 + r)*64 + q*4);
            As[(q*4+0)*PITCH + r] = fmaxf(p.x*sc[0] + sh[0], 0.0f);
            As[(q*4+1)*PITCH + r] = fmaxf(p.y*sc[1] + sh[1], 0.0f);
            As[(q*4+2)*PITCH + r] = fmaxf(p.z*sc[2] + sh[2], 0.0f);
            As[(q*4+3)*PITCH + r] = fmaxf(p.w*sc[3] + sh[3], 0.0f);
        }
    }
    __syncthreads();
    int rg = tid >> 3, cg = tid & 7;
    float acc[4][8];
    #pragma unroll
    for (int i = 0; i < 4; i++)
        #pragma unroll
        for (int j = 0; j < 8; j++) acc[i][j] = 0.0f;
    gemm_kloop(As, Wlo, Whi, rg, cg, acc);
    float bb[8];
    #pragma unroll
    for (int j = 0; j < 8; j++) bb[j] = b2[c0 + cg*8 + j];
    #pragma unroll
    for (int i = 0; i < 4; i++)
        #pragma unroll
        for (int j = 0; j < 8; j++) acc[i][j] += bb[j];
    // per-thread max/min over its 4 rows (all in group rg>>3)
    float mx8[8], mn8[8];
    #pragma unroll
    for (int j = 0; j < 8; j++) { mx8[j] = acc[0][j]; mn8[j] = acc[0][j]; }
    #pragma unroll
    for (int i = 1; i < 4; i++)
        #pragma unroll
        for (int j = 0; j < 8; j++) {
            mx8[j] = fmaxf(mx8[j], acc[i][j]);
            mn8[j] = fminf(mn8[j], acc[i][j]);
        }
    __syncthreads();     // done reading As
    // layout in As region: rS[64*33] rQ[64*33] rmax[32*65] rmin[32*65]
    float* rS   = As;
    float* rQ   = As + 64*33;
    float* rmax = As + 2*64*33;
    float* rmin = rmax + 32*65;
    {
        float s8[8], q8[8];
        #pragma unroll
        for (int j = 0; j < 8; j++) { s8[j] = 0.0f; q8[j] = 0.0f; }
        #pragma unroll
        for (int i = 0; i < 4; i++)
            #pragma unroll
            for (int j = 0; j < 8; j++) { s8[j] += acc[i][j]; q8[j] += acc[i][j]*acc[i][j]; }
        #pragma unroll
        for (int j = 0; j < 8; j++) {
            rS[(cg*8 + j)*33 + rg] = s8[j];
            rQ[(cg*8 + j)*33 + rg] = q8[j];
            rmax[rg*65 + cg*8 + j] = mx8[j];
            rmin[rg*65 + cg*8 + j] = mn8[j];
        }
    }
    __syncthreads();
    if (tid < 64) {
        float s = 0.0f, q = 0.0f;
        #pragma unroll 8
        for (int r = 0; r < 32; r++) { s += rS[tid*33 + r]; q += rQ[tid*33 + r]; }
        g_pS[blockIdx.x*128 + c0 + tid] = s;
        g_pQ[blockIdx.x*128 + c0 + tid] = q;
    }
    {
        int g = tid >> 6, c = tid & 63;     // 4 groups x 64 cols
        float mx = rmax[(g*8 + 0)*65 + c];
        float mn = rmin[(g*8 + 0)*65 + c];
        #pragma unroll
        for (int u = 1; u < 8; u++) {
            mx = fmaxf(mx, rmax[(g*8 + u)*65 + c]);
            mn = fminf(mn, rmin[(g*8 + u)*65 + c]);
        }
        size_t grp = (size_t)blockIdx.x*4 + g;    // = b*NP + s
        g_gmax[grp*128 + c0 + c] = mx;
        g_gmin[grp*128 + c0 + c] = mn;
    }
}

// ---------------------------------------------------------------------------
// 7) finalize stats: double-precision reduce of nblk float partials / channel
// ---------------------------------------------------------------------------
__global__ void finalize_stats_kernel(int C, int nblk) {
    __shared__ double shs[512], shq[512];
    int tid = threadIdx.x;                    // 512 threads
    int c   = tid & (C - 1);
    int rep = tid / C;
    int nrep = 512 / C;
    int per  = nblk / nrep;
    double s = 0.0, q = 0.0;
    for (int b = rep*per; b < (rep+1)*per; b++) {
        s += (double)g_pS[b*C + c];
        q += (double)g_pQ[b*C + c];
    }
    shs[tid] = s; shq[tid] = q;
    __syncthreads();
    if (rep == 0) {
        for (int r = 1; r < nrep; r++) { s += shs[r*C + c]; q += shq[r*C + c]; }
        double n = (double)M_TOTAL;
        double m = s / n;
        double var = q / n - m*m;
        g_mu[c] = (float)m;
        g_rs[c] = (float)(1.0 / sqrt(var + 1e-5));
    }
}

// ---------------------------------------------------------------------------
// 8) final: BN2+ReLU on group extrema, transpose -> out [B,128,NP]
// ---------------------------------------------------------------------------
__global__ void final_out_kernel(const float* __restrict__ gam2,
                                 const float* __restrict__ bet2,
                                 float* __restrict__ out) {
    extern __shared__ float sh[];             // [128 c][129]
    int b  = blockIdx.x;
    int s0 = blockIdx.y * 128;
    int tid = threadIdx.x;                    // 256
    for (int i = tid; i < 128*128; i += 256) {
        int s = i >> 7, c = i & 127;
        float slope = g_rs[c]*gam2[c];
        size_t gidx = ((size_t)(b*NP + s0 + s))*128 + c;
        float raw = (slope >= 0.0f) ? g_gmax[gidx] : g_gmin[gidx];
        float v = (raw - g_mu[c])*slope + bet2[c];
        sh[c*129 + s] = fmaxf(v, 0.0f);
    }
    __syncthreads();
    float* ob = out + (size_t)BB*3*NP + (size_t)b*128*NP + s0;
    for (int i = tid; i < 128*128; i += 256) {
        int c = i >> 7, s = i & 127;
        ob[(size_t)c*NP + s] = sh[c*129 + s];
    }
}

// ---------------------------------------------------------------------------
extern "C" void kernel_launch(void* const* d_in, const int* in_sizes, int n_in,
                              void* d_out, int out_size) {
    const float* xyz = (const float*)d_in[0];
    const float* pts = (const float*)d_in[1];
    const float* w0  = (const float*)d_in[2];
    const float* b0  = (const float*)d_in[3];
    const float* g0  = (const float*)d_in[4];
    const float* be0 = (const float*)d_in[5];
    const float* w1  = (const float*)d_in[6];
    const float* b1  = (const float*)d_in[7];
    const float* g1  = (const float*)d_in[8];
    const float* be1 = (const float*)d_in[9];
    const float* w2  = (const float*)d_in[10];
    const float* b2  = (const float*)d_in[11];
    const float* g2  = (const float*)d_in[12];
    const float* be2 = (const float*)d_in[13];
    float* out = (float*)d_out;

    const int smemG = (64*PITCH + 64*64) * 4;   // 50176 B
    const int smemF = 128*129*4;                // 66048 B
    cudaFuncSetAttribute(pgemm_kernel, cudaFuncAttributeMaxDynamicSharedMemorySize, smemG);
    cudaFuncSetAttribute(gemm1_kernel, cudaFuncAttributeMaxDynamicSharedMemorySize, smemG);
    cudaFuncSetAttribute(gemm2_kernel, cudaFuncAttributeMaxDynamicSharedMemorySize, smemG);
    cudaFuncSetAttribute(final_out_kernel, cudaFuncAttributeMaxDynamicSharedMemorySize, smemF);

    fps_kernel<<<16, 512>>>(xyz, out);
    ball_query_kernel<<<2048, 256>>>(xyz);
    pgemm_kernel<<<512, 256, smemG>>>(pts, w0, b0);

    stats0_kernel<<<2048, 256>>>(xyz, w0);
    finalize_stats_kernel<<<1, 512>>>(64, 2048);

    gemm1_kernel<<<4096, 256, smemG>>>(xyz, w0, w1, b1, g0, be0);
    finalize_stats_kernel<<<1, 512>>>(64, 4096);

    gemm2_kernel<<<dim3(4096, 2), 256, smemG>>>(w2, b2, g1, be1);
    finalize_stats_kernel<<<1, 512>>>(128, 4096);

    final_out_kernel<<<dim3(16, 8), 256, smemF>>>(g2, be2, out);
}

// round 5
// speedup vs baseline: 1.4864x; 1.1054x over previous
#include <cuda_runtime.h>
#include <math.h>
#include <stdint.h>

#define BB 16
#define NN 4096
#define NP 1024
#define NS 32
#define M_TOTAL (BB*NP*NS)   /* 524288 */
#define P2 132               /* k-major A pitch, 128-row tiles */
#define P1 260               /* k-major A pitch, 256-row tiles */

// ---------------------------------------------------------------------------
// Scratch
// ---------------------------------------------------------------------------
__device__ float g_P[(size_t)BB*NN*64];       // pts-part of layer0   16.8 MB
__device__ float g_new_xyz[BB*NP*3];
__device__ int   g_idx[M_TOTAL];
__device__ float g_y1[(size_t)M_TOTAL*64];    // layer1 pre-BN       134 MB
__device__ float g_gmax[(size_t)BB*NP*128];   // per-group raw max     8 MB
__device__ float g_gmin[(size_t)BB*NP*128];   // per-group raw min     8 MB
__device__ float g_pS[4096*128];
__device__ float g_pQ[4096*128];
__device__ float g_mu[128];
__device__ float g_rs[128];

// ---------------------------------------------------------------------------
// 1) FPS: 512 thr, 8 pts/thread, ONE barrier per iteration.
//    Double-buffered warp partials; every warp redundantly does the final
//    16-way reduce so no broadcast barrier is needed.
// ---------------------------------------------------------------------------
__global__ void fps_kernel(const float* __restrict__ xyz, float* __restrict__ out) {
    int b = blockIdx.x, tid = threadIdx.x;     // 512 threads
    int lane = tid & 31, wp = tid >> 5;
    const float* xb = xyz + (size_t)b*3*NN;
    float px[8], py[8], pz[8], dd[8];
    #pragma unroll
    for (int i = 0; i < 8; i++) {
        int n = tid + i*512;
        px[i] = xb[n]; py[i] = xb[NN+n]; pz[i] = xb[2*NN+n];
        dd[i] = 1e10f;
    }
    __shared__ unsigned s_wv[2][16];
    __shared__ int      s_wi[2][16];
    __shared__ int      s_fps[NP];
    if (tid == 0) s_fps[0] = 0;
    int far = 0;
    for (int it = 1; it < NP; ++it) {
        float cx = __ldg(xb + far);
        float cy = __ldg(xb + NN + far);
        float cz = __ldg(xb + 2*NN + far);
        unsigned bv = 0u, bi = 0x7fffffffu;
        #pragma unroll
        for (int i = 0; i < 8; i++) {
            float dx = __fsub_rn(px[i], cx);
            float dy = __fsub_rn(py[i], cy);
            float dz = __fsub_rn(pz[i], cz);
            float d  = __fadd_rn(__fadd_rn(__fmul_rn(dx,dx), __fmul_rn(dy,dy)),
                                 __fmul_rn(dz,dz));
            dd[i] = fminf(dd[i], d);
            unsigned vb = __float_as_uint(dd[i]);
            if (vb > bv) { bv = vb; bi = (unsigned)(tid + i*512); }
        }
        unsigned wmax = __reduce_max_sync(0xffffffffu, bv);
        unsigned cand = (bv == wmax) ? bi : 0x7fffffffu;
        unsigned wi   = __reduce_min_sync(0xffffffffu, cand);
        int buf = it & 1;
        if (lane == 0) { s_wv[buf][wp] = wmax; s_wi[buf][wp] = (int)wi; }
        __syncthreads();
        unsigned v  = (lane < 16) ? s_wv[buf][lane] : 0u;
        unsigned ix = (lane < 16) ? (unsigned)s_wi[buf][lane] : 0x7fffffffu;
        unsigned m2 = __reduce_max_sync(0xffffffffu, v);
        unsigned c2 = (v == m2) ? ix : 0x7fffffffu;
        far = (int)__reduce_min_sync(0xffffffffu, c2);
        if (tid == 0) s_fps[it] = far;
    }
    __syncthreads();
    for (int s = tid; s < NP; s += 512) {
        int j = s_fps[s];
        float x = xb[j], y = xb[NN+j], z = xb[2*NN+j];
        out[(size_t)b*3*NP + s]        = x;
        out[(size_t)b*3*NP + NP + s]   = y;
        out[(size_t)b*3*NP + 2*NP + s] = z;
        float* nx = g_new_xyz + ((size_t)b*NP + s)*3;
        nx[0] = x; nx[1] = y; nx[2] = z;
    }
}

// ---------------------------------------------------------------------------
// 2) Ball query (unchanged)
// ---------------------------------------------------------------------------
__global__ void ball_query_kernel(const float* __restrict__ xyz) {
    int gt   = blockIdx.x * blockDim.x + threadIdx.x;
    int warp = gt >> 5;
    int lane = gt & 31;
    if (warp >= BB*NP) return;
    int b = warp >> 10;
    const float* xb = xyz + (size_t)b*3*NN;
    const float* nx = g_new_xyz + (size_t)warp*3;
    float cx = nx[0], cy = nx[1], cz = nx[2];
    float ssrc = __fadd_rn(__fadd_rn(__fmul_rn(cx,cx), __fmul_rn(cy,cy)), __fmul_rn(cz,cz));
    const float R2 = 0.04f;
    int cnt = 0, first = -1;
    int* op = g_idx + (size_t)warp*NS;
    for (int j0 = 0; j0 < NN && cnt < NS; j0 += 32) {
        int j = j0 + lane;
        float x = xb[j], y = xb[NN+j], z = xb[2*NN+j];
        float sdst = __fadd_rn(__fadd_rn(__fmul_rn(x,x), __fmul_rn(y,y)), __fmul_rn(z,z));
        float dot  = __fadd_rn(__fadd_rn(__fmul_rn(cx,x), __fmul_rn(cy,y)), __fmul_rn(cz,z));
        float d = __fadd_rn(__fadd_rn(__fmul_rn(-2.0f, dot), ssrc), sdst);
        bool in = !(d > R2);
        unsigned m = __ballot_sync(0xffffffffu, in);
        if (first < 0 && m) first = j0 + __ffs(m) - 1;
        if (in) {
            int slot = cnt + __popc(m & ((1u << lane) - 1u));
            if (slot < NS) op[slot] = j;
        }
        cnt += __popc(m);
    }
    if (cnt < NS) {
        if (first < 0) first = NN - 1;
        for (int slot = cnt + lane; slot < NS; slot += 32) op[slot] = first;
    }
}

// ---------------------------------------------------------------------------
#define FMA8(a, w0, w1, accrow) \
    accrow[0] += a*w0.x; accrow[1] += a*w0.y; accrow[2] += a*w0.z; accrow[3] += a*w0.w; \
    accrow[4] += a*w1.x; accrow[5] += a*w1.y; accrow[6] += a*w1.z; accrow[7] += a*w1.w;

// 4x8 kloop (pgemm only), A pitch P2
__device__ __forceinline__ void gemm_kloop48(const float* __restrict__ As,
                                             const float* __restrict__ Wlo,
                                             const float* __restrict__ Whi,
                                             int rg, int cg, float acc[4][8]) {
    const float* ap = As + rg*4;
    const float* wl = Wlo + cg*4;
    const float* wh = Whi + cg*4;
    #pragma unroll 8
    for (int k = 0; k < 64; ++k) {
        float4 a  = *(const float4*)(ap + k*P2);
        float4 w0 = *(const float4*)(wl + k*32);
        float4 w1 = *(const float4*)(wh + k*32);
        FMA8(a.x, w0, w1, acc[0]);
        FMA8(a.y, w0, w1, acc[1]);
        FMA8(a.z, w0, w1, acc[2]);
        FMA8(a.w, w0, w1, acc[3]);
    }
}

// W fill: [64][64] global slice -> Wlo/Whi [64][32]
__device__ __forceinline__ void fill_w64(float* Wlo, float* Whi,
                                         const float* __restrict__ w, int ldw,
                                         int c0, int tid) {
    for (int i = tid; i < 64*64; i += 256) {
        int k = i >> 6, c = i & 63;
        float v = w[k*ldw + c0 + c];
        int cgg = c >> 3, t = c & 7;
        if (t < 4) Wlo[k*32 + cgg*4 + t]     = v;
        else       Whi[k*32 + cgg*4 + t - 4] = v;
    }
}

// ---------------------------------------------------------------------------
// 3) P = pts^T @ W0[3:67] + b0   (per batch: 4096x64 @ 64x64)
// ---------------------------------------------------------------------------
__global__ void __launch_bounds__(256, 4)
pgemm_kernel(const float* __restrict__ pts, const float* __restrict__ w0,
             const float* __restrict__ b0) {
    extern __shared__ __align__(16) float sm[];
    float* As  = sm;                 // [64][P2]
    float* Wlo = sm + 64*P2;
    float* Whi = Wlo + 64*32;
    int tid = threadIdx.x;
    int bx  = blockIdx.x;
    int b   = bx >> 5;
    int n0  = (bx & 31) * 128;
    fill_w64(Wlo, Whi, w0 + 3*64, 64, 0, tid);
    const float* pb = pts + (size_t)b*64*NN;
    for (int i = tid; i < 64*128; i += 256) {
        int c = i >> 7, r = i & 127;
        As[c*P2 + r] = pb[(size_t)c*NN + n0 + r];
    }
    __syncthreads();
    int rg = tid >> 3, cg = tid & 7;
    float acc[4][8];
    #pragma unroll
    for (int i = 0; i < 4; i++)
        #pragma unroll
        for (int j = 0; j < 8; j++) acc[i][j] = 0.0f;
    gemm_kloop48(As, Wlo, Whi, rg, cg, acc);
    float bb[8];
    #pragma unroll
    for (int j = 0; j < 8; j++) bb[j] = b0[cg*8 + j];
    #pragma unroll
    for (int i = 0; i < 4; i++) {
        size_t row = (size_t)b*NN + n0 + rg*4 + i;
        float4 v0 = make_float4(acc[i][0]+bb[0], acc[i][1]+bb[1], acc[i][2]+bb[2], acc[i][3]+bb[3]);
        float4 v1 = make_float4(acc[i][4]+bb[4], acc[i][5]+bb[5], acc[i][6]+bb[6], acc[i][7]+bb[7]);
        *(float4*)&g_P[row*64 + cg*8]     = v0;
        *(float4*)&g_P[row*64 + cg*8 + 4] = v1;
    }
}

// ---------------------------------------------------------------------------
// 4) stats of y0 (never materialized): y0 = P[j] + dxyz . W0[0:3]
// ---------------------------------------------------------------------------
__global__ void __launch_bounds__(256)
stats0_kernel(const float* __restrict__ xyz, const float* __restrict__ w0) {
    __shared__ float sdx[256], sdy[256], sdz[256];
    __shared__ int   sj[256];
    __shared__ __align__(16) float s_w0[192];
    __shared__ float redS[64*17], redQ[64*17];
    int tid = threadIdx.x;
    int m0  = blockIdx.x * 256;
    int b   = m0 >> 15;
    if (tid < 192) s_w0[tid] = w0[tid];
    {
        int r = tid;
        int j = g_idx[m0 + r];
        sj[r] = j;
        const float* xb = xyz + (size_t)b*3*NN;
        const float* nx = g_new_xyz + (size_t)((m0 + r) >> 5)*3;
        sdx[r] = __fsub_rn(xb[j],      nx[0]);
        sdy[r] = __fsub_rn(xb[NN+j],   nx[1]);
        sdz[r] = __fsub_rn(xb[2*NN+j], nx[2]);
    }
    __syncthreads();
    int q  = tid >> 4;
    int rl = tid & 15;
    float4 wx = *(const float4*)(s_w0 + q*4);
    float4 wy = *(const float4*)(s_w0 + 64 + q*4);
    float4 wz = *(const float4*)(s_w0 + 128 + q*4);
    float sx=0,sy=0,sz=0,sw=0, qx=0,qy=0,qz=0,qw=0;
    const float* Pb = g_P + (size_t)b*NN*64;
    for (int n = 0; n < 16; n++) {
        int r = rl + n*16;
        float4 p = *(const float4*)(Pb + (size_t)sj[r]*64 + q*4);
        float dx = sdx[r], dy = sdy[r], dz = sdz[r];
        float yx = p.x + dx*wx.x + dy*wy.x + dz*wz.x;
        float yy = p.y + dx*wx.y + dy*wy.y + dz*wz.y;
        float yz = p.z + dx*wx.z + dy*wy.z + dz*wz.z;
        float yw = p.w + dx*wx.w + dy*wy.w + dz*wz.w;
        sx += yx; sy += yy; sz += yz; sw += yw;
        qx += yx*yx; qy += yy*yy; qz += yz*yz; qw += yw*yw;
    }
    redS[(4*q+0)*17 + rl] = sx; redQ[(4*q+0)*17 + rl] = qx;
    redS[(4*q+1)*17 + rl] = sy; redQ[(4*q+1)*17 + rl] = qy;
    redS[(4*q+2)*17 + rl] = sz; redQ[(4*q+2)*17 + rl] = qz;
    redS[(4*q+3)*17 + rl] = sw; redQ[(4*q+3)*17 + rl] = qw;
    __syncthreads();
    if (tid < 64) {
        float ss = 0.0f, sq = 0.0f;
        #pragma unroll
        for (int u = 0; u < 16; u++) { ss += redS[tid*17+u]; sq += redQ[tid*17+u]; }
        g_pS[blockIdx.x*64 + tid] = ss;
        g_pQ[blockIdx.x*64 + tid] = sq;
    }
}

// ---------------------------------------------------------------------------
// 5) layer1: 256x64 tile, 8x8 acc. A = BN0+ReLU(y0 on the fly), y1 = A@W1+b1
// ---------------------------------------------------------------------------
__global__ void __launch_bounds__(256, 2)
gemm1_kernel(const float* __restrict__ xyz, const float* __restrict__ w0,
             const float* __restrict__ w1, const float* __restrict__ b1,
             const float* __restrict__ gam0, const float* __restrict__ bet0) {
    extern __shared__ __align__(16) float sm[];
    float* As  = sm;                 // [64][P1]
    float* Wlo = sm + 64*P1;         // [64][32]
    float* Whi = Wlo + 64*32;
    __shared__ float sdx[256], sdy[256], sdz[256];
    __shared__ int   sj[256];
    __shared__ __align__(16) float s_w0[192];
    int tid = threadIdx.x;
    int m0  = blockIdx.x * 256;
    int b   = m0 >> 15;
    fill_w64(Wlo, Whi, w1, 64, 0, tid);
    if (tid < 192) s_w0[tid] = w0[tid];
    {
        int r = tid;
        int j = g_idx[m0 + r];
        sj[r] = j;
        const float* xb = xyz + (size_t)b*3*NN;
        const float* nx = g_new_xyz + (size_t)((m0 + r) >> 5)*3;
        sdx[r] = __fsub_rn(xb[j],      nx[0]);
        sdy[r] = __fsub_rn(xb[NN+j],   nx[1]);
        sdz[r] = __fsub_rn(xb[2*NN+j], nx[2]);
    }
    __syncthreads();
    {
        int q  = tid >> 4;    // channel group 0..15
        int rl = tid & 15;
        float4 wx = *(const float4*)(s_w0 + q*4);
        float4 wy = *(const float4*)(s_w0 + 64 + q*4);
        float4 wz = *(const float4*)(s_w0 + 128 + q*4);
        float sc[4], sh[4];
        #pragma unroll
        for (int t = 0; t < 4; t++) {
            int k = q*4 + t;
            sc[t] = g_rs[k]*gam0[k];
            sh[t] = bet0[k] - g_mu[k]*sc[t];
        }
        const float* Pb = g_P + (size_t)b*NN*64;
        for (int n = 0; n < 16; n++) {
            int r = rl + n*16;
            float4 p = *(const float4*)(Pb + (size_t)sj[r]*64 + q*4);
            float dx = sdx[r], dy = sdy[r], dz = sdz[r];
            float y0 = p.x + dx*wx.x + dy*wy.x + dz*wz.x;
            float yb = p.y + dx*wx.y + dy*wy.y + dz*wz.y;
            float yc = p.z + dx*wx.z + dy*wy.z + dz*wz.z;
            float yd = p.w + dx*wx.w + dy*wy.w + dz*wz.w;
            As[(q*4+0)*P1 + r] = fmaxf(y0*sc[0] + sh[0], 0.0f);
            As[(q*4+1)*P1 + r] = fmaxf(yb*sc[1] + sh[1], 0.0f);
            As[(q*4+2)*P1 + r] = fmaxf(yc*sc[2] + sh[2], 0.0f);
            As[(q*4+3)*P1 + r] = fmaxf(yd*sc[3] + sh[3], 0.0f);
        }
    }
    __syncthreads();
    int rg = tid >> 3, cg = tid & 7;       // rg 0..31 (8 rows), cg 0..7 (8 cols)
    float acc[8][8];
    #pragma unroll
    for (int i = 0; i < 8; i++)
        #pragma unroll
        for (int j = 0; j < 8; j++) acc[i][j] = 0.0f;
    {
        const float* ap = As + rg*8;
        const float* wl = Wlo + cg*4;
        const float* wh = Whi + cg*4;
        #pragma unroll 4
        for (int k = 0; k < 64; ++k) {
            float4 a0 = *(const float4*)(ap + k*P1);
            float4 a1 = *(const float4*)(ap + k*P1 + 4);
            float4 w0v = *(const float4*)(wl + k*32);
            float4 w1v = *(const float4*)(wh + k*32);
            FMA8(a0.x, w0v, w1v, acc[0]);
            FMA8(a0.y, w0v, w1v, acc[1]);
            FMA8(a0.z, w0v, w1v, acc[2]);
            FMA8(a0.w, w0v, w1v, acc[3]);
            FMA8(a1.x, w0v, w1v, acc[4]);
            FMA8(a1.y, w0v, w1v, acc[5]);
            FMA8(a1.z, w0v, w1v, acc[6]);
            FMA8(a1.w, w0v, w1v, acc[7]);
        }
    }
    float bb[8];
    #pragma unroll
    for (int j = 0; j < 8; j++) bb[j] = b1[cg*8 + j];
    #pragma unroll
    for (int i = 0; i < 8; i++)
        #pragma unroll
        for (int j = 0; j < 8; j++) acc[i][j] += bb[j];
    #pragma unroll
    for (int i = 0; i < 8; i++) {
        size_t row = (size_t)(m0 + rg*8 + i);
        float4 v0 = make_float4(acc[i][0], acc[i][1], acc[i][2], acc[i][3]);
        float4 v1 = make_float4(acc[i][4], acc[i][5], acc[i][6], acc[i][7]);
        *(float4*)&g_y1[row*64 + cg*8]     = v0;
        *(float4*)&g_y1[row*64 + cg*8 + 4] = v1;
    }
    // stats partials
    float s8[8], q8[8];
    #pragma unroll
    for (int j = 0; j < 8; j++) { s8[j] = 0.0f; q8[j] = 0.0f; }
    #pragma unroll
    for (int i = 0; i < 8; i++)
        #pragma unroll
        for (int j = 0; j < 8; j++) { s8[j] += acc[i][j]; q8[j] += acc[i][j]*acc[i][j]; }
    __syncthreads();
    float* rS = As;            // [64][33]
    float* rQ = As + 64*33;
    #pragma unroll
    for (int j = 0; j < 8; j++) {
        rS[(cg*8 + j)*33 + rg] = s8[j];
        rQ[(cg*8 + j)*33 + rg] = q8[j];
    }
    __syncthreads();
    if (tid < 64) {
        float s = 0.0f, q = 0.0f;
        #pragma unroll 8
        for (int r = 0; r < 32; r++) { s += rS[tid*33 + r]; q += rQ[tid*33 + r]; }
        g_pS[blockIdx.x*64 + tid] = s;
        g_pQ[blockIdx.x*64 + tid] = q;
    }
}

// ---------------------------------------------------------------------------
// 6) layer2: 128x128 tile, 8x8 acc. A = BN1+ReLU(y1) (read once),
//    epilogue: stats + per-group(32-row) raw max/min.
// ---------------------------------------------------------------------------
__global__ void __launch_bounds__(256, 2)
gemm2_kernel(const float* __restrict__ w2, const float* __restrict__ b2,
             const float* __restrict__ gam1, const float* __restrict__ bet1) {
    extern __shared__ __align__(16) float sm[];
    float* As  = sm;                 // [64][P2]
    float* Wlo = sm + 64*P2;         // [64][64]
    float* Whi = Wlo + 64*64;        // [64][64]
    int tid = threadIdx.x;
    int m0  = blockIdx.x * 128;
    // W fill: [64][128] -> Wlo/Whi [64][64]
    for (int i = tid; i < 64*128; i += 256) {
        int k = i >> 7, c = i & 127;
        float v = w2[k*128 + c];
        int cgg = c >> 3, t = c & 7;
        if (t < 4) Wlo[k*64 + cgg*4 + t]     = v;
        else       Whi[k*64 + cgg*4 + t - 4] = v;
    }
    {
        int q  = tid >> 4;
        int rl = tid & 15;
        float sc[4], sh[4];
        #pragma unroll
        for (int t = 0; t < 4; t++) {
            int k = q*4 + t;
            sc[t] = g_rs[k]*gam1[k];
            sh[t] = bet1[k] - g_mu[k]*sc[t];
        }
        for (int n = 0; n < 8; n++) {
            int r = rl + n*16;
            float4 p = *(const float4*)(g_y1 + (size_t)(m0 + r)*64 + q*4);
            As[(q*4+0)*P2 + r] = fmaxf(p.x*sc[0] + sh[0], 0.0f);
            As[(q*4+1)*P2 + r] = fmaxf(p.y*sc[1] + sh[1], 0.0f);
            As[(q*4+2)*P2 + r] = fmaxf(p.z*sc[2] + sh[2], 0.0f);
            As[(q*4+3)*P2 + r] = fmaxf(p.w*sc[3] + sh[3], 0.0f);
        }
    }
    __syncthreads();
    int rg = tid >> 4, cg = tid & 15;      // rg 0..15 (8 rows), cg 0..15 (8 cols)
    float acc[8][8];
    #pragma unroll
    for (int i = 0; i < 8; i++)
        #pragma unroll
        for (int j = 0; j < 8; j++) acc[i][j] = 0.0f;
    {
        const float* ap = As + rg*8;
        const float* wl = Wlo + cg*4;
        const float* wh = Whi + cg*4;
        #pragma unroll 4
        for (int k = 0; k < 64; ++k) {
            float4 a0 = *(const float4*)(ap + k*P2);
            float4 a1 = *(const float4*)(ap + k*P2 + 4);
            float4 w0v = *(const float4*)(wl + k*64);
            float4 w1v = *(const float4*)(wh + k*64);
            FMA8(a0.x, w0v, w1v, acc[0]);
            FMA8(a0.y, w0v, w1v, acc[1]);
            FMA8(a0.z, w0v, w1v, acc[2]);
            FMA8(a0.w, w0v, w1v, acc[3]);
            FMA8(a1.x, w0v, w1v, acc[4]);
            FMA8(a1.y, w0v, w1v, acc[5]);
            FMA8(a1.z, w0v, w1v, acc[6]);
            FMA8(a1.w, w0v, w1v, acc[7]);
        }
    }
    float bb[8];
    #pragma unroll
    for (int j = 0; j < 8; j++) bb[j] = b2[cg*8 + j];
    #pragma unroll
    for (int i = 0; i < 8; i++)
        #pragma unroll
        for (int j = 0; j < 8; j++) acc[i][j] += bb[j];
    // per-thread stats + max/min over its 8 rows (all in group rg>>2)
    float s8[8], q8[8], mx8[8], mn8[8];
    #pragma unroll
    for (int j = 0; j < 8; j++) {
        s8[j] = acc[0][j]; q8[j] = acc[0][j]*acc[0][j];
        mx8[j] = acc[0][j]; mn8[j] = acc[0][j];
    }
    #pragma unroll
    for (int i = 1; i < 8; i++)
        #pragma unroll
        for (int j = 0; j < 8; j++) {
            s8[j] += acc[i][j]; q8[j] += acc[i][j]*acc[i][j];
            mx8[j] = fmaxf(mx8[j], acc[i][j]);
            mn8[j] = fminf(mn8[j], acc[i][j]);
        }
    __syncthreads();          // done reading As / W
    float* rS   = As;                // [128][17]
    float* rQ   = As + 128*17;       // [128][17]
    float* rmax = Wlo;               // [16][132]
    float* rmin = Whi;               // [16][132]
    #pragma unroll
    for (int j = 0; j < 8; j++) {
        rS[(cg*8 + j)*17 + rg] = s8[j];
        rQ[(cg*8 + j)*17 + rg] = q8[j];
        rmax[rg*132 + cg*8 + j] = mx8[j];
        rmin[rg*132 + cg*8 + j] = mn8[j];
    }
    __syncthreads();
    if (tid < 128) {
        float s = 0.0f, q = 0.0f;
        #pragma unroll
        for (int r = 0; r < 16; r++) { s += rS[tid*17 + r]; q += rQ[tid*17 + r]; }
        g_pS[blockIdx.x*128 + tid] = s;
        g_pQ[blockIdx.x*128 + tid] = q;
    }
    for (int i = tid; i < 512; i += 256) {
        int g = i >> 7, c = i & 127;
        float mx = rmax[(g*4 + 0)*132 + c];
        float mn = rmin[(g*4 + 0)*132 + c];
        #pragma unroll
        for (int u = 1; u < 4; u++) {
            mx = fmaxf(mx, rmax[(g*4 + u)*132 + c]);
            mn = fminf(mn, rmin[(g*4 + u)*132 + c]);
        }
        size_t grp = (size_t)blockIdx.x*4 + g;    // = b*NP + s
        g_gmax[grp*128 + c] = mx;
        g_gmin[grp*128 + c] = mn;
    }
}

// ---------------------------------------------------------------------------
// 7) finalize stats
// ---------------------------------------------------------------------------
__global__ void finalize_stats_kernel(int C, int nblk) {
    __shared__ double shs[512], shq[512];
    int tid = threadIdx.x;                    // 512 threads
    int c   = tid & (C - 1);
    int rep = tid / C;
    int nrep = 512 / C;
    int per  = nblk / nrep;
    double s = 0.0, q = 0.0;
    for (int b = rep*per; b < (rep+1)*per; b++) {
        s += (double)g_pS[b*C + c];
        q += (double)g_pQ[b*C + c];
    }
    shs[tid] = s; shq[tid] = q;
    __syncthreads();
    if (rep == 0) {
        for (int r = 1; r < nrep; r++) { s += shs[r*C + c]; q += shq[r*C + c]; }
        double n = (double)M_TOTAL;
        double m = s / n;
        double var = q / n - m*m;
        g_mu[c] = (float)m;
        g_rs[c] = (float)(1.0 / sqrt(var + 1e-5));
    }
}

// ---------------------------------------------------------------------------
// 8) final: BN2+ReLU on group extrema, transpose -> out [B,128,NP]
// ---------------------------------------------------------------------------
__global__ void final_out_kernel(const float* __restrict__ gam2,
                                 const float* __restrict__ bet2,
                                 float* __restrict__ out) {
    extern __shared__ float sh[];             // [128 c][129]
    int b  = blockIdx.x;
    int s0 = blockIdx.y * 128;
    int tid = threadIdx.x;                    // 256
    for (int i = tid; i < 128*128; i += 256) {
        int s = i >> 7, c = i & 127;
        float slope = g_rs[c]*gam2[c];
        size_t gidx = ((size_t)(b*NP + s0 + s))*128 + c;
        float raw = (slope >= 0.0f) ? g_gmax[gidx] : g_gmin[gidx];
        float v = (raw - g_mu[c])*slope + bet2[c];
        sh[c*129 + s] = fmaxf(v, 0.0f);
    }
    __syncthreads();
    float* ob = out + (size_t)BB*3*NP + (size_t)b*128*NP + s0;
    for (int i = tid; i < 128*128; i += 256) {
        int c = i >> 7, s = i & 127;
        ob[(size_t)c*NP + s] = sh[c*129 + s];
    }
}

// ---------------------------------------------------------------------------
extern "C" void kernel_launch(void* const* d_in, const int* in_sizes, int n_in,
                              void* d_out, int out_size) {
    const float* xyz = (const float*)d_in[0];
    const float* pts = (const float*)d_in[1];
    const float* w0  = (const float*)d_in[2];
    const float* b0  = (const float*)d_in[3];
    const float* g0  = (const float*)d_in[4];
    const float* be0 = (const float*)d_in[5];
    const float* w1  = (const float*)d_in[6];
    const float* b1  = (const float*)d_in[7];
    const float* g1  = (const float*)d_in[8];
    const float* be1 = (const float*)d_in[9];
    const float* w2  = (const float*)d_in[10];
    const float* b2  = (const float*)d_in[11];
    const float* g2  = (const float*)d_in[12];
    const float* be2 = (const float*)d_in[13];
    float* out = (float*)d_out;

    const int smemP = (64*P2 + 64*64) * 4;        // 50176 B
    const int smem1 = (64*P1 + 64*64) * 4;        // 82944 B
    const int smem2 = (64*P2 + 2*64*64) * 4;      // 66560 B
    const int smemF = 128*129*4;                  // 66048 B
    cudaFuncSetAttribute(pgemm_kernel, cudaFuncAttributeMaxDynamicSharedMemorySize, smemP);
    cudaFuncSetAttribute(gemm1_kernel, cudaFuncAttributeMaxDynamicSharedMemorySize, smem1);
    cudaFuncSetAttribute(gemm2_kernel, cudaFuncAttributeMaxDynamicSharedMemorySize, smem2);
    cudaFuncSetAttribute(final_out_kernel, cudaFuncAttributeMaxDynamicSharedMemorySize, smemF);

    fps_kernel<<<16, 512>>>(xyz, out);
    ball_query_kernel<<<2048, 256>>>(xyz);
    pgemm_kernel<<<512, 256, smemP>>>(pts, w0, b0);

    stats0_kernel<<<2048, 256>>>(xyz, w0);
    finalize_stats_kernel<<<1, 512>>>(64, 2048);

    gemm1_kernel<<<2048, 256, smem1>>>(xyz, w0, w1, b1, g0, be0);
    finalize_stats_kernel<<<1, 512>>>(64, 2048);

    gemm2_kernel<<<4096, 256, smem2>>>(w2, b2, g1, be1);
    finalize_stats_kernel<<<1, 512>>>(128, 4096);

    final_out_kernel<<<dim3(16, 8), 256, smemF>>>(g2, be2, out);
}

// round 6
// speedup vs baseline: 1.5219x; 1.0238x over previous
#include <cuda_runtime.h>
#include <math.h>
#include <stdint.h>

#define BB 16
#define NN 4096
#define NP 1024
#define NS 32
#define M_TOTAL (BB*NP*NS)   /* 524288 */
#define PP 132               /* pgemm A pitch (128 rows + pad) */
#define P1 260               /* gemm1 A pitch (256 rows + pad) */
#define P2D 264              /* gemm2 A pitch (128 rows DUPLICATED + pad) */

typedef unsigned long long ull;

// ---------------------------------------------------------------------------
// Packed f32x2 helpers (bit-identical to 2x scalar fma.rn)
// ---------------------------------------------------------------------------
__device__ __forceinline__ void ffma2(ull& acc, ull a, ull w) {
    asm("fma.rn.f32x2 %0, %1, %2, %0;" : "+l"(acc) : "l"(a), "l"(w));
}
__device__ __forceinline__ ull pack2(float x) {
    ull r;
    asm("mov.b64 %0, {%1, %1};" : "=l"(r) : "f"(x));
    return r;
}
__device__ __forceinline__ float2 unpack2(ull v) {
    float2 r;
    asm("mov.b64 {%0, %1}, %2;" : "=f"(r.x), "=f"(r.y) : "l"(v));
    return r;
}

// ---------------------------------------------------------------------------
// Scratch
// ---------------------------------------------------------------------------
__device__ float g_P[(size_t)BB*NN*64];       // pts-part of layer0   16.8 MB
__device__ float g_new_xyz[BB*NP*3];
__device__ int   g_idx[M_TOTAL];
__device__ float g_y1[(size_t)M_TOTAL*64];    // layer1 pre-BN       134 MB
__device__ float g_gmax[(size_t)BB*NP*128];
__device__ float g_gmin[(size_t)BB*NP*128];
__device__ float g_pS[4096*128];
__device__ float g_pQ[4096*128];
__device__ float g_mu[128];
__device__ float g_rs[128];

// ---------------------------------------------------------------------------
// 1) FPS: 1024 thr, 4 pts/thread, one barrier per iteration.
// ---------------------------------------------------------------------------
__global__ void __launch_bounds__(1024, 1)
fps_kernel(const float* __restrict__ xyz, float* __restrict__ out) {
    int b = blockIdx.x, tid = threadIdx.x;     // 1024 threads
    int lane = tid & 31, wp = tid >> 5;
    const float* xb = xyz + (size_t)b*3*NN;
    float px[4], py[4], pz[4], dd[4];
    #pragma unroll
    for (int i = 0; i < 4; i++) {
        int n = tid + i*1024;
        px[i] = xb[n]; py[i] = xb[NN+n]; pz[i] = xb[2*NN+n];
        dd[i] = 1e10f;
    }
    __shared__ unsigned s_wv[2][32];
    __shared__ int      s_wi[2][32];
    __shared__ int      s_fps[NP];
    if (tid == 0) s_fps[0] = 0;
    int far = 0;
    for (int it = 1; it < NP; ++it) {
        float cx = __ldg(xb + far);
        float cy = __ldg(xb + NN + far);
        float cz = __ldg(xb + 2*NN + far);
        unsigned bv = 0u, bi = 0x7fffffffu;
        #pragma unroll
        for (int i = 0; i < 4; i++) {
            float dx = __fsub_rn(px[i], cx);
            float dy = __fsub_rn(py[i], cy);
            float dz = __fsub_rn(pz[i], cz);
            float d  = __fadd_rn(__fadd_rn(__fmul_rn(dx,dx), __fmul_rn(dy,dy)),
                                 __fmul_rn(dz,dz));
            dd[i] = fminf(dd[i], d);
            unsigned vb = __float_as_uint(dd[i]);
            if (vb > bv) { bv = vb; bi = (unsigned)(tid + i*1024); }
        }
        unsigned wmax = __reduce_max_sync(0xffffffffu, bv);
        unsigned cand = (bv == wmax) ? bi : 0x7fffffffu;
        unsigned wi   = __reduce_min_sync(0xffffffffu, cand);
        int buf = it & 1;
        if (lane == 0) { s_wv[buf][wp] = wmax; s_wi[buf][wp] = (int)wi; }
        __syncthreads();
        unsigned v  = s_wv[buf][lane];
        unsigned ix = (unsigned)s_wi[buf][lane];
        unsigned m2 = __reduce_max_sync(0xffffffffu, v);
        unsigned c2 = (v == m2) ? ix : 0x7fffffffu;
        far = (int)__reduce_min_sync(0xffffffffu, c2);
        if (tid == 0) s_fps[it] = far;
    }
    __syncthreads();
    for (int s = tid; s < NP; s += 1024) {
        int j = s_fps[s];
        float x = xb[j], y = xb[NN+j], z = xb[2*NN+j];
        out[(size_t)b*3*NP + s]        = x;
        out[(size_t)b*3*NP + NP + s]   = y;
        out[(size_t)b*3*NP + 2*NP + s] = z;
        float* nx = g_new_xyz + ((size_t)b*NP + s)*3;
        nx[0] = x; nx[1] = y; nx[2] = z;
    }
}

// ---------------------------------------------------------------------------
// 2) Ball query (unchanged)
// ---------------------------------------------------------------------------
__global__ void ball_query_kernel(const float* __restrict__ xyz) {
    int gt   = blockIdx.x * blockDim.x + threadIdx.x;
    int warp = gt >> 5;
    int lane = gt & 31;
    if (warp >= BB*NP) return;
    int b = warp >> 10;
    const float* xb = xyz + (size_t)b*3*NN;
    const float* nx = g_new_xyz + (size_t)warp*3;
    float cx = nx[0], cy = nx[1], cz = nx[2];
    float ssrc = __fadd_rn(__fadd_rn(__fmul_rn(cx,cx), __fmul_rn(cy,cy)), __fmul_rn(cz,cz));
    const float R2 = 0.04f;
    int cnt = 0, first = -1;
    int* op = g_idx + (size_t)warp*NS;
    for (int j0 = 0; j0 < NN && cnt < NS; j0 += 32) {
        int j = j0 + lane;
        float x = xb[j], y = xb[NN+j], z = xb[2*NN+j];
        float sdst = __fadd_rn(__fadd_rn(__fmul_rn(x,x), __fmul_rn(y,y)), __fmul_rn(z,z));
        float dot  = __fadd_rn(__fadd_rn(__fmul_rn(cx,x), __fmul_rn(cy,y)), __fmul_rn(cz,z));
        float d = __fadd_rn(__fadd_rn(__fmul_rn(-2.0f, dot), ssrc), sdst);
        bool in = !(d > R2);
        unsigned m = __ballot_sync(0xffffffffu, in);
        if (first < 0 && m) first = j0 + __ffs(m) - 1;
        if (in) {
            int slot = cnt + __popc(m & ((1u << lane) - 1u));
            if (slot < NS) op[slot] = j;
        }
        cnt += __popc(m);
    }
    if (cnt < NS) {
        if (first < 0) first = NN - 1;
        for (int slot = cnt + lane; slot < NS; slot += 32) op[slot] = first;
    }
}

// ---------------------------------------------------------------------------
#define FMA8(a, w0, w1, accrow) \
    accrow[0] += a*w0.x; accrow[1] += a*w0.y; accrow[2] += a*w0.z; accrow[3] += a*w0.w; \
    accrow[4] += a*w1.x; accrow[5] += a*w1.y; accrow[6] += a*w1.z; accrow[7] += a*w1.w;

// W fill: [64][ldw] global slice -> Wlo/Whi [64][32]
__device__ __forceinline__ void fill_w64(float* Wlo, float* Whi,
                                         const float* __restrict__ w, int ldw,
                                         int c0, int tid) {
    for (int i = tid; i < 64*64; i += 256) {
        int k = i >> 6, c = i & 63;
        float v = w[k*ldw + c0 + c];
        int cgg = c >> 3, t = c & 7;
        if (t < 4) Wlo[k*32 + cgg*4 + t]     = v;
        else       Whi[k*32 + cgg*4 + t - 4] = v;
    }
}

// ---------------------------------------------------------------------------
// 3) P = pts^T @ W0[3:67] + b0  (scalar path; small)
// ---------------------------------------------------------------------------
__global__ void __launch_bounds__(256, 4)
pgemm_kernel(const float* __restrict__ pts, const float* __restrict__ w0,
             const float* __restrict__ b0) {
    extern __shared__ __align__(16) float sm[];
    float* As  = sm;                 // [64][PP]
    float* Wlo = sm + 64*PP;
    float* Whi = Wlo + 64*32;
    int tid = threadIdx.x;
    int bx  = blockIdx.x;
    int b   = bx >> 5;
    int n0  = (bx & 31) * 128;
    fill_w64(Wlo, Whi, w0 + 3*64, 64, 0, tid);
    const float* pb = pts + (size_t)b*64*NN;
    for (int i = tid; i < 64*128; i += 256) {
        int c = i >> 7, r = i & 127;
        As[c*PP + r] = pb[(size_t)c*NN + n0 + r];
    }
    __syncthreads();
    int rg = tid >> 3, cg = tid & 7;
    float acc[4][8];
    #pragma unroll
    for (int i = 0; i < 4; i++)
        #pragma unroll
        for (int j = 0; j < 8; j++) acc[i][j] = 0.0f;
    {
        const float* ap = As + rg*4;
        const float* wl = Wlo + cg*4;
        const float* wh = Whi + cg*4;
        #pragma unroll 8
        for (int k = 0; k < 64; ++k) {
            float4 a  = *(const float4*)(ap + k*PP);
            float4 w0v = *(const float4*)(wl + k*32);
            float4 w1v = *(const float4*)(wh + k*32);
            FMA8(a.x, w0v, w1v, acc[0]);
            FMA8(a.y, w0v, w1v, acc[1]);
            FMA8(a.z, w0v, w1v, acc[2]);
            FMA8(a.w, w0v, w1v, acc[3]);
        }
    }
    float bb[8];
    #pragma unroll
    for (int j = 0; j < 8; j++) bb[j] = b0[cg*8 + j];
    #pragma unroll
    for (int i = 0; i < 4; i++) {
        size_t row = (size_t)b*NN + n0 + rg*4 + i;
        float4 v0 = make_float4(acc[i][0]+bb[0], acc[i][1]+bb[1], acc[i][2]+bb[2], acc[i][3]+bb[3]);
        float4 v1 = make_float4(acc[i][4]+bb[4], acc[i][5]+bb[5], acc[i][6]+bb[6], acc[i][7]+bb[7]);
        *(float4*)&g_P[row*64 + cg*8]     = v0;
        *(float4*)&g_P[row*64 + cg*8 + 4] = v1;
    }
}

// ---------------------------------------------------------------------------
// 4) stats of y0 (never materialized): y0 = P[j] + dxyz . W0[0:3]
// ---------------------------------------------------------------------------
__global__ void __launch_bounds__(256)
stats0_kernel(const float* __restrict__ xyz, const float* __restrict__ w0) {
    __shared__ float sdx[256], sdy[256], sdz[256];
    __shared__ int   sj[256];
    __shared__ __align__(16) float s_w0[192];
    __shared__ float redS[64*17], redQ[64*17];
    int tid = threadIdx.x;
    int m0  = blockIdx.x * 256;
    int b   = m0 >> 15;
    if (tid < 192) s_w0[tid] = w0[tid];
    {
        int r = tid;
        int j = g_idx[m0 + r];
        sj[r] = j;
        const float* xb = xyz + (size_t)b*3*NN;
        const float* nx = g_new_xyz + (size_t)((m0 + r) >> 5)*3;
        sdx[r] = __fsub_rn(xb[j],      nx[0]);
        sdy[r] = __fsub_rn(xb[NN+j],   nx[1]);
        sdz[r] = __fsub_rn(xb[2*NN+j], nx[2]);
    }
    __syncthreads();
    int q  = tid >> 4;
    int rl = tid & 15;
    float4 wx = *(const float4*)(s_w0 + q*4);
    float4 wy = *(const float4*)(s_w0 + 64 + q*4);
    float4 wz = *(const float4*)(s_w0 + 128 + q*4);
    float sx=0,sy=0,sz=0,sw=0, qx=0,qy=0,qz=0,qw=0;
    const float* Pb = g_P + (size_t)b*NN*64;
    for (int n = 0; n < 16; n++) {
        int r = rl + n*16;
        float4 p = *(const float4*)(Pb + (size_t)sj[r]*64 + q*4);
        float dx = sdx[r], dy = sdy[r], dz = sdz[r];
        float yx = p.x + dx*wx.x + dy*wy.x + dz*wz.x;
        float yy = p.y + dx*wx.y + dy*wy.y + dz*wz.y;
        float yz = p.z + dx*wx.z + dy*wy.z + dz*wz.z;
        float yw = p.w + dx*wx.w + dy*wy.w + dz*wz.w;
        sx += yx; sy += yy; sz += yz; sw += yw;
        qx += yx*yx; qy += yy*yy; qz += yz*yz; qw += yw*yw;
    }
    redS[(4*q+0)*17 + rl] = sx; redQ[(4*q+0)*17 + rl] = qx;
    redS[(4*q+1)*17 + rl] = sy; redQ[(4*q+1)*17 + rl] = qy;
    redS[(4*q+2)*17 + rl] = sz; redQ[(4*q+2)*17 + rl] = qz;
    redS[(4*q+3)*17 + rl] = sw; redQ[(4*q+3)*17 + rl] = qw;
    __syncthreads();
    if (tid < 64) {
        float ss = 0.0f, sq = 0.0f;
        #pragma unroll
        for (int u = 0; u < 16; u++) { ss += redS[tid*17+u]; sq += redQ[tid*17+u]; }
        g_pS[blockIdx.x*64 + tid] = ss;
        g_pQ[blockIdx.x*64 + tid] = sq;
    }
}

// ---------------------------------------------------------------------------
// 5) layer1: 256x64 tile, packed-f32x2 8x8 acc. A = BN0+ReLU(y0 on the fly).
// ---------------------------------------------------------------------------
__global__ void __launch_bounds__(256, 2)
gemm1_kernel(const float* __restrict__ xyz, const float* __restrict__ w0,
             const float* __restrict__ w1, const float* __restrict__ b1,
             const float* __restrict__ gam0, const float* __restrict__ bet0) {
    extern __shared__ __align__(16) float sm[];
    float* As  = sm;                 // [64][P1]
    float* Wlo = sm + 64*P1;         // [64][32]
    float* Whi = Wlo + 64*32;
    __shared__ float sdx[256], sdy[256], sdz[256];
    __shared__ int   sj[256];
    __shared__ __align__(16) float s_w0[192];
    int tid = threadIdx.x;
    int m0  = blockIdx.x * 256;
    int b   = m0 >> 15;
    fill_w64(Wlo, Whi, w1, 64, 0, tid);
    if (tid < 192) s_w0[tid] = w0[tid];
    {
        int r = tid;
        int j = g_idx[m0 + r];
        sj[r] = j;
        const float* xb = xyz + (size_t)b*3*NN;
        const float* nx = g_new_xyz + (size_t)((m0 + r) >> 5)*3;
        sdx[r] = __fsub_rn(xb[j],      nx[0]);
        sdy[r] = __fsub_rn(xb[NN+j],   nx[1]);
        sdz[r] = __fsub_rn(xb[2*NN+j], nx[2]);
    }
    __syncthreads();
    {
        int q  = tid >> 4;
        int rl = tid & 15;
        float4 wx = *(const float4*)(s_w0 + q*4);
        float4 wy = *(const float4*)(s_w0 + 64 + q*4);
        float4 wz = *(const float4*)(s_w0 + 128 + q*4);
        float sc[4], sh[4];
        #pragma unroll
        for (int t = 0; t < 4; t++) {
            int k = q*4 + t;
            sc[t] = g_rs[k]*gam0[k];
            sh[t] = bet0[k] - g_mu[k]*sc[t];
        }
        const float* Pb = g_P + (size_t)b*NN*64;
        for (int n = 0; n < 16; n++) {
            int r = rl + n*16;
            float4 p = *(const float4*)(Pb + (size_t)sj[r]*64 + q*4);
            float dx = sdx[r], dy = sdy[r], dz = sdz[r];
            float y0 = p.x + dx*wx.x + dy*wy.x + dz*wz.x;
            float yb = p.y + dx*wx.y + dy*wy.y + dz*wz.y;
            float yc = p.z + dx*wx.z + dy*wy.z + dz*wz.z;
            float yd = p.w + dx*wx.w + dy*wy.w + dz*wz.w;
            As[(q*4+0)*P1 + r] = fmaxf(y0*sc[0] + sh[0], 0.0f);
            As[(q*4+1)*P1 + r] = fmaxf(yb*sc[1] + sh[1], 0.0f);
            As[(q*4+2)*P1 + r] = fmaxf(yc*sc[2] + sh[2], 0.0f);
            As[(q*4+3)*P1 + r] = fmaxf(yd*sc[3] + sh[3], 0.0f);
        }
    }
    __syncthreads();
    int rg = tid >> 3, cg = tid & 7;
    ull acc2[8][4];
    #pragma unroll
    for (int i = 0; i < 8; i++)
        #pragma unroll
        for (int p = 0; p < 4; p++) acc2[i][p] = 0ull;
    {
        const float* ap = As + rg*8;
        const char* wlb = (const char*)(Wlo + cg*4);
        const char* whb = (const char*)(Whi + cg*4);
        #pragma unroll 4
        for (int k = 0; k < 64; ++k) {
            float4 a0 = *(const float4*)(ap + k*P1);
            float4 a1 = *(const float4*)(ap + k*P1 + 4);
            ulonglong2 w0v = *(const ulonglong2*)(wlb + k*128);
            ulonglong2 w1v = *(const ulonglong2*)(whb + k*128);
            ull pa;
            pa = pack2(a0.x);
            ffma2(acc2[0][0], pa, w0v.x); ffma2(acc2[0][1], pa, w0v.y);
            ffma2(acc2[0][2], pa, w1v.x); ffma2(acc2[0][3], pa, w1v.y);
            pa = pack2(a0.y);
            ffma2(acc2[1][0], pa, w0v.x); ffma2(acc2[1][1], pa, w0v.y);
            ffma2(acc2[1][2], pa, w1v.x); ffma2(acc2[1][3], pa, w1v.y);
            pa = pack2(a0.z);
            ffma2(acc2[2][0], pa, w0v.x); ffma2(acc2[2][1], pa, w0v.y);
            ffma2(acc2[2][2], pa, w1v.x); ffma2(acc2[2][3], pa, w1v.y);
            pa = pack2(a0.w);
            ffma2(acc2[3][0], pa, w0v.x); ffma2(acc2[3][1], pa, w0v.y);
            ffma2(acc2[3][2], pa, w1v.x); ffma2(acc2[3][3], pa, w1v.y);
            pa = pack2(a1.x);
            ffma2(acc2[4][0], pa, w0v.x); ffma2(acc2[4][1], pa, w0v.y);
            ffma2(acc2[4][2], pa, w1v.x); ffma2(acc2[4][3], pa, w1v.y);
            pa = pack2(a1.y);
            ffma2(acc2[5][0], pa, w0v.x); ffma2(acc2[5][1], pa, w0v.y);
            ffma2(acc2[5][2], pa, w1v.x); ffma2(acc2[5][3], pa, w1v.y);
            pa = pack2(a1.z);
            ffma2(acc2[6][0], pa, w0v.x); ffma2(acc2[6][1], pa, w0v.y);
            ffma2(acc2[6][2], pa, w1v.x); ffma2(acc2[6][3], pa, w1v.y);
            pa = pack2(a1.w);
            ffma2(acc2[7][0], pa, w0v.x); ffma2(acc2[7][1], pa, w0v.y);
            ffma2(acc2[7][2], pa, w1v.x); ffma2(acc2[7][3], pa, w1v.y);
        }
    }
    float acc[8][8];
    #pragma unroll
    for (int i = 0; i < 8; i++)
        #pragma unroll
        for (int p = 0; p < 4; p++) {
            float2 u = unpack2(acc2[i][p]);
            acc[i][2*p] = u.x; acc[i][2*p+1] = u.y;
        }
    float bb[8];
    #pragma unroll
    for (int j = 0; j < 8; j++) bb[j] = b1[cg*8 + j];
    #pragma unroll
    for (int i = 0; i < 8; i++)
        #pragma unroll
        for (int j = 0; j < 8; j++) acc[i][j] += bb[j];
    #pragma unroll
    for (int i = 0; i < 8; i++) {
        size_t row = (size_t)(m0 + rg*8 + i);
        float4 v0 = make_float4(acc[i][0], acc[i][1], acc[i][2], acc[i][3]);
        float4 v1 = make_float4(acc[i][4], acc[i][5], acc[i][6], acc[i][7]);
        *(float4*)&g_y1[row*64 + cg*8]     = v0;
        *(float4*)&g_y1[row*64 + cg*8 + 4] = v1;
    }
    float s8[8], q8[8];
    #pragma unroll
    for (int j = 0; j < 8; j++) { s8[j] = 0.0f; q8[j] = 0.0f; }
    #pragma unroll
    for (int i = 0; i < 8; i++)
        #pragma unroll
        for (int j = 0; j < 8; j++) { s8[j] += acc[i][j]; q8[j] += acc[i][j]*acc[i][j]; }
    __syncthreads();
    float* rS = As;            // [64][33]
    float* rQ = As + 64*33;
    #pragma unroll
    for (int j = 0; j < 8; j++) {
        rS[(cg*8 + j)*33 + rg] = s8[j];
        rQ[(cg*8 + j)*33 + rg] = q8[j];
    }
    __syncthreads();
    if (tid < 64) {
        float s = 0.0f, q = 0.0f;
        #pragma unroll 8
        for (int r = 0; r < 32; r++) { s += rS[tid*33 + r]; q += rQ[tid*33 + r]; }
        g_pS[blockIdx.x*64 + tid] = s;
        g_pQ[blockIdx.x*64 + tid] = q;
    }
}

// ---------------------------------------------------------------------------
// 6) layer2: 128x128 tile, A stored DUPLICATED -> pure packed inner loop.
// ---------------------------------------------------------------------------
__global__ void __launch_bounds__(256, 2)
gemm2_kernel(const float* __restrict__ w2, const float* __restrict__ b2,
             const float* __restrict__ gam1, const float* __restrict__ bet1) {
    extern __shared__ __align__(16) float sm[];
    float* As  = sm;                 // [64][P2D]  (values duplicated: (a,a))
    float* Wlo = sm + 64*P2D;        // [64][64]
    float* Whi = Wlo + 64*64;        // [64][64]
    int tid = threadIdx.x;
    int m0  = blockIdx.x * 128;
    for (int i = tid; i < 64*128; i += 256) {
        int k = i >> 7, c = i & 127;
        float v = w2[k*128 + c];
        int cgg = c >> 3, t = c & 7;
        if (t < 4) Wlo[k*64 + cgg*4 + t]     = v;
        else       Whi[k*64 + cgg*4 + t - 4] = v;
    }
    {
        int q  = tid >> 4;
        int rl = tid & 15;
        float sc[4], sh[4];
        #pragma unroll
        for (int t = 0; t < 4; t++) {
            int k = q*4 + t;
            sc[t] = g_rs[k]*gam1[k];
            sh[t] = bet1[k] - g_mu[k]*sc[t];
        }
        for (int n = 0; n < 8; n++) {
            int r = rl + n*16;
            float4 p = *(const float4*)(g_y1 + (size_t)(m0 + r)*64 + q*4);
            float v0 = fmaxf(p.x*sc[0] + sh[0], 0.0f);
            float v1 = fmaxf(p.y*sc[1] + sh[1], 0.0f);
            float v2 = fmaxf(p.z*sc[2] + sh[2], 0.0f);
            float v3 = fmaxf(p.w*sc[3] + sh[3], 0.0f);
            *(float2*)(As + (q*4+0)*P2D + 2*r) = make_float2(v0, v0);
            *(float2*)(As + (q*4+1)*P2D + 2*r) = make_float2(v1, v1);
            *(float2*)(As + (q*4+2)*P2D + 2*r) = make_float2(v2, v2);
            *(float2*)(As + (q*4+3)*P2D + 2*r) = make_float2(v3, v3);
        }
    }
    __syncthreads();
    int rg = tid >> 4, cg = tid & 15;      // rg 0..15 (8 rows), cg 0..15 (8 cols)
    ull acc2[8][4];
    #pragma unroll
    for (int i = 0; i < 8; i++)
        #pragma unroll
        for (int p = 0; p < 4; p++) acc2[i][p] = 0ull;
    {
        const char* ap  = (const char*)(As + rg*16);
        const char* wlb = (const char*)(Wlo + cg*4);
        const char* whb = (const char*)(Whi + cg*4);
        #pragma unroll 4
        for (int k = 0; k < 64; ++k) {
            ulonglong2 a01 = *(const ulonglong2*)(ap + k*(P2D*4));
            ulonglong2 a23 = *(const ulonglong2*)(ap + k*(P2D*4) + 16);
            ulonglong2 a45 = *(const ulonglong2*)(ap + k*(P2D*4) + 32);
            ulonglong2 a67 = *(const ulonglong2*)(ap + k*(P2D*4) + 48);
            ulonglong2 w0v = *(const ulonglong2*)(wlb + k*256);
            ulonglong2 w1v = *(const ulonglong2*)(whb + k*256);
            ffma2(acc2[0][0], a01.x, w0v.x); ffma2(acc2[0][1], a01.x, w0v.y);
            ffma2(acc2[0][2], a01.x, w1v.x); ffma2(acc2[0][3], a01.x, w1v.y);
            ffma2(acc2[1][0], a01.y, w0v.x); ffma2(acc2[1][1], a01.y, w0v.y);
            ffma2(acc2[1][2], a01.y, w1v.x); ffma2(acc2[1][3], a01.y, w1v.y);
            ffma2(acc2[2][0], a23.x, w0v.x); ffma2(acc2[2][1], a23.x, w0v.y);
            ffma2(acc2[2][2], a23.x, w1v.x); ffma2(acc2[2][3], a23.x, w1v.y);
            ffma2(acc2[3][0], a23.y, w0v.x); ffma2(acc2[3][1], a23.y, w0v.y);
            ffma2(acc2[3][2], a23.y, w1v.x); ffma2(acc2[3][3], a23.y, w1v.y);
            ffma2(acc2[4][0], a45.x, w0v.x); ffma2(acc2[4][1], a45.x, w0v.y);
            ffma2(acc2[4][2], a45.x, w1v.x); ffma2(acc2[4][3], a45.x, w1v.y);
            ffma2(acc2[5][0], a45.y, w0v.x); ffma2(acc2[5][1], a45.y, w0v.y);
            ffma2(acc2[5][2], a45.y, w1v.x); ffma2(acc2[5][3], a45.y, w1v.y);
            ffma2(acc2[6][0], a67.x, w0v.x); ffma2(acc2[6][1], a67.x, w0v.y);
            ffma2(acc2[6][2], a67.x, w1v.x); ffma2(acc2[6][3], a67.x, w1v.y);
            ffma2(acc2[7][0], a67.y, w0v.x); ffma2(acc2[7][1], a67.y, w0v.y);
            ffma2(acc2[7][2], a67.y, w1v.x); ffma2(acc2[7][3], a67.y, w1v.y);
        }
    }
    float acc[8][8];
    #pragma unroll
    for (int i = 0; i < 8; i++)
        #pragma unroll
        for (int p = 0; p < 4; p++) {
            float2 u = unpack2(acc2[i][p]);
            acc[i][2*p] = u.x; acc[i][2*p+1] = u.y;
        }
    float bb[8];
    #pragma unroll
    for (int j = 0; j < 8; j++) bb[j] = b2[cg*8 + j];
    #pragma unroll
    for (int i = 0; i < 8; i++)
        #pragma unroll
        for (int j = 0; j < 8; j++) acc[i][j] += bb[j];
    float s8[8], q8[8], mx8[8], mn8[8];
    #pragma unroll
    for (int j = 0; j < 8; j++) {
        s8[j] = acc[0][j]; q8[j] = acc[0][j]*acc[0][j];
        mx8[j] = acc[0][j]; mn8[j] = acc[0][j];
    }
    #pragma unroll
    for (int i = 1; i < 8; i++)
        #pragma unroll
        for (int j = 0; j < 8; j++) {
            s8[j] += acc[i][j]; q8[j] += acc[i][j]*acc[i][j];
            mx8[j] = fmaxf(mx8[j], acc[i][j]);
            mn8[j] = fminf(mn8[j], acc[i][j]);
        }
    __syncthreads();
    float* rS   = As;                // [128][17]
    float* rQ   = As + 128*17;
    float* rmax = Wlo;               // [16][132]
    float* rmin = Whi;
    #pragma unroll
    for (int j = 0; j < 8; j++) {
        rS[(cg*8 + j)*17 + rg] = s8[j];
        rQ[(cg*8 + j)*17 + rg] = q8[j];
        rmax[rg*132 + cg*8 + j] = mx8[j];
        rmin[rg*132 + cg*8 + j] = mn8[j];
    }
    __syncthreads();
    if (tid < 128) {
        float s = 0.0f, q = 0.0f;
        #pragma unroll
        for (int r = 0; r < 16; r++) { s += rS[tid*17 + r]; q += rQ[tid*17 + r]; }
        g_pS[blockIdx.x*128 + tid] = s;
        g_pQ[blockIdx.x*128 + tid] = q;
    }
    for (int i = tid; i < 512; i += 256) {
        int g = i >> 7, c = i & 127;
        float mx = rmax[(g*4 + 0)*132 + c];
        float mn = rmin[(g*4 + 0)*132 + c];
        #pragma unroll
        for (int u = 1; u < 4; u++) {
            mx = fmaxf(mx, rmax[(g*4 + u)*132 + c]);
            mn = fminf(mn, rmin[(g*4 + u)*132 + c]);
        }
        size_t grp = (size_t)blockIdx.x*4 + g;
        g_gmax[grp*128 + c] = mx;
        g_gmin[grp*128 + c] = mn;
    }
}

// ---------------------------------------------------------------------------
// 7) finalize stats
// ---------------------------------------------------------------------------
__global__ void finalize_stats_kernel(int C, int nblk) {
    __shared__ double shs[512], shq[512];
    int tid = threadIdx.x;
    int c   = tid & (C - 1);
    int rep = tid / C;
    int nrep = 512 / C;
    int per  = nblk / nrep;
    double s = 0.0, q = 0.0;
    for (int b = rep*per; b < (rep+1)*per; b++) {
        s += (double)g_pS[b*C + c];
        q += (double)g_pQ[b*C + c];
    }
    shs[tid] = s; shq[tid] = q;
    __syncthreads();
    if (rep == 0) {
        for (int r = 1; r < nrep; r++) { s += shs[r*C + c]; q += shq[r*C + c]; }
        double n = (double)M_TOTAL;
        double m = s / n;
        double var = q / n - m*m;
        g_mu[c] = (float)m;
        g_rs[c] = (float)(1.0 / sqrt(var + 1e-5));
    }
}

// ---------------------------------------------------------------------------
// 8) final: BN2+ReLU on group extrema, transpose -> out [B,128,NP]
// ---------------------------------------------------------------------------
__global__ void final_out_kernel(const float* __restrict__ gam2,
                                 const float* __restrict__ bet2,
                                 float* __restrict__ out) {
    extern __shared__ float sh[];             // [128 c][129]
    int b  = blockIdx.x;
    int s0 = blockIdx.y * 128;
    int tid = threadIdx.x;                    // 256
    for (int i = tid; i < 128*128; i += 256) {
        int s = i >> 7, c = i & 127;
        float slope = g_rs[c]*gam2[c];
        size_t gidx = ((size_t)(b*NP + s0 + s))*128 + c;
        float raw = (slope >= 0.0f) ? g_gmax[gidx] : g_gmin[gidx];
        float v = (raw - g_mu[c])*slope + bet2[c];
        sh[c*129 + s] = fmaxf(v, 0.0f);
    }
    __syncthreads();
    float* ob = out + (size_t)BB*3*NP + (size_t)b*128*NP + s0;
    for (int i = tid; i < 128*128; i += 256) {
        int c = i >> 7, s = i & 127;
        ob[(size_t)c*NP + s] = sh[c*129 + s];
    }
}

// ---------------------------------------------------------------------------
extern "C" void kernel_launch(void* const* d_in, const int* in_sizes, int n_in,
                              void* d_out, int out_size) {
    const float* xyz = (const float*)d_in[0];
    const float* pts = (const float*)d_in[1];
    const float* w0  = (const float*)d_in[2];
    const float* b0  = (const float*)d_in[3];
    const float* g0  = (const float*)d_in[4];
    const float* be0 = (const float*)d_in[5];
    const float* w1  = (const float*)d_in[6];
    const float* b1  = (const float*)d_in[7];
    const float* g1  = (const float*)d_in[8];
    const float* be1 = (const float*)d_in[9];
    const float* w2  = (const float*)d_in[10];
    const float* b2  = (const float*)d_in[11];
    const float* g2  = (const float*)d_in[12];
    const float* be2 = (const float*)d_in[13];
    float* out = (float*)d_out;

    const int smemP = (64*PP  + 64*64) * 4;       // 50176 B
    const int smem1 = (64*P1  + 64*64) * 4;       // 82944 B
    const int smem2 = (64*P2D + 2*64*64) * 4;     // 100352 B
    const int smemF = 128*129*4;                  // 66048 B
    cudaFuncSetAttribute(pgemm_kernel, cudaFuncAttributeMaxDynamicSharedMemorySize, smemP);
    cudaFuncSetAttribute(gemm1_kernel, cudaFuncAttributeMaxDynamicSharedMemorySize, smem1);
    cudaFuncSetAttribute(gemm2_kernel, cudaFuncAttributeMaxDynamicSharedMemorySize, smem2);
    cudaFuncSetAttribute(final_out_kernel, cudaFuncAttributeMaxDynamicSharedMemorySize, smemF);

    fps_kernel<<<16, 1024>>>(xyz, out);
    ball_query_kernel<<<2048, 256>>>(xyz);
    pgemm_kernel<<<512, 256, smemP>>>(pts, w0, b0);

    stats0_kernel<<<2048, 256>>>(xyz, w0);
    finalize_stats_kernel<<<1, 512>>>(64, 2048);

    gemm1_kernel<<<2048, 256, smem1>>>(xyz, w0, w1, b1, g0, be0);
    finalize_stats_kernel<<<1, 512>>>(64, 2048);

    gemm2_kernel<<<4096, 256, smem2>>>(w2, b2, g1, be1);
    finalize_stats_kernel<<<1, 512>>>(128, 4096);

    final_out_kernel<<<dim3(16, 8), 256, smemF>>>(g2, be2, out);
}